// round 4
// baseline (speedup 1.0000x reference)
#include <cuda_runtime.h>
#include <cuda_bf16.h>
#include <math.h>

// Problem constants: N=50000 nodes, F_IN=128, H=256, C=32.
#define MAXN 50000
#define HDIM 256

// Scratch (no allocations allowed). Referenced only from device code.
__device__ float g_deg[MAXN];
__device__ float g_dinv[MAXN];
__device__ float g_H[MAXN * HDIM];   // GEMM output (messages source)
__device__ float g_A[MAXN * HDIM];   // aggregated output

// ---------------------------------------------------------------------------
// Degree / normalization   (edge_index is int32: JAX x64-disabled randint)
// ---------------------------------------------------------------------------
__global__ void init_deg_kernel(int n) {
    int i = blockIdx.x * blockDim.x + threadIdx.x;
    if (i < n) g_deg[i] = 1.0f;  // self-loop contributes 1
}

__global__ void deg_edges_kernel(const int* __restrict__ dst, int e) {
    int i = blockIdx.x * blockDim.x + threadIdx.x;
    if (i < e) atomicAdd(&g_deg[dst[i]], 1.0f);
}

__global__ void dinv_kernel(int n) {
    int i = blockIdx.x * blockDim.x + threadIdx.x;
    if (i < n) g_dinv[i] = rsqrtf(g_deg[i]);  // deg >= 1 always
}

// ---------------------------------------------------------------------------
// Tiled fp32 GEMM core: C[M,N] = op(A)[M,K] @ B[K,N] (+ bias).
// ---------------------------------------------------------------------------
template <int BM, int BN, int BK, int TM, int TN, bool RELU, bool BIAS>
__device__ __forceinline__ void gemm_core(const float* __restrict__ A,
                                          const float* __restrict__ B,
                                          const float* __restrict__ bias,
                                          float* __restrict__ C,
                                          int M, int K, int N) {
    constexpr int THREADS = (BM / TM) * (BN / TN);
    __shared__ float As[BK][BM + 4];
    __shared__ float Bs[BK][BN + 4];

    const int tid = threadIdx.x;
    const int tx = tid % (BN / TN);
    const int ty = tid / (BN / TN);
    const int row0 = blockIdx.x * BM;
    const int col0 = blockIdx.y * BN;

    float acc[TM][TN];
#pragma unroll
    for (int m = 0; m < TM; m++)
#pragma unroll
        for (int n = 0; n < TN; n++) acc[m][n] = 0.0f;

    for (int k0 = 0; k0 < K; k0 += BK) {
        // A tile (BM x BK) stored transposed for stride-1 compute reads.
#pragma unroll
        for (int i = tid; i < BM * BK; i += THREADS) {
            int r = i / BK, c = i % BK;
            int gr = row0 + r;
            float v = (gr < M) ? A[(size_t)gr * K + (k0 + c)] : 0.0f;
            if (RELU) v = fmaxf(v, 0.0f);
            As[c][r] = v;
        }
        // B tile (BK x BN)
#pragma unroll
        for (int i = tid; i < BK * BN; i += THREADS) {
            int r = i / BN, c = i % BN;
            int gc = col0 + c;
            Bs[r][c] = (gc < N) ? B[(size_t)(k0 + r) * N + gc] : 0.0f;
        }
        __syncthreads();

#pragma unroll
        for (int kk = 0; kk < BK; kk++) {
            float ra[TM], rb[TN];
#pragma unroll
            for (int m = 0; m < TM; m++) ra[m] = As[kk][ty * TM + m];
#pragma unroll
            for (int n = 0; n < TN; n++) rb[n] = Bs[kk][tx * TN + n];
#pragma unroll
            for (int m = 0; m < TM; m++)
#pragma unroll
                for (int n = 0; n < TN; n++) acc[m][n] = fmaf(ra[m], rb[n], acc[m][n]);
        }
        __syncthreads();
    }

#pragma unroll
    for (int m = 0; m < TM; m++) {
        int gr = row0 + ty * TM + m;
        if (gr >= M) continue;
#pragma unroll
        for (int n = 0; n < TN; n++) {
            int gc = col0 + tx * TN + n;
            if (gc < N) {
                float v = acc[m][n];
                if (BIAS) v += bias[gc];
                C[(size_t)gr * N + gc] = v;
            }
        }
    }
}

// Thin wrappers binding scratch globals (device-side addressing only).
__global__ void gemm1_kernel(const float* __restrict__ x,
                             const float* __restrict__ W1, int M) {
    gemm_core<128, 128, 16, 8, 8, false, false>(x, W1, nullptr, g_H, M, 128, HDIM);
}

__global__ void gemm2_kernel(const float* __restrict__ W2, int M) {
    gemm_core<128, 128, 16, 8, 8, true, false>(g_A, W2, nullptr, g_H, M, HDIM, HDIM);
}

__global__ void gemm3_kernel(const float* __restrict__ Wc,
                             const float* __restrict__ bc,
                             float* __restrict__ out, int M, int C) {
    gemm_core<64, 32, 16, 4, 2, true, true>(g_A, Wc, bc, out, M, HDIM, C);
}

// ---------------------------------------------------------------------------
// Aggregation: g_A[i,:] = b[:] + dinv[i]^2 * g_H[i,:]  (self-loop + bias)
// ---------------------------------------------------------------------------
__global__ void agg_init_kernel(const float* __restrict__ bias, int n) {
    int i = blockIdx.x;
    int j = threadIdx.x;
    if (i >= n) return;
    float di = g_dinv[i];
    g_A[(size_t)i * HDIM + j] = bias[j] + di * di * g_H[(size_t)i * HDIM + j];
}

// One block per edge: g_A[dst,:] += norm * g_H[src,:]
__global__ void scatter_kernel(const int* __restrict__ src,
                               const int* __restrict__ dst, int e) {
    int ed = blockIdx.x;
    if (ed >= e) return;
    int s = src[ed];
    int d = dst[ed];
    float norm = g_dinv[s] * g_dinv[d];
    int j = threadIdx.x;
    float v = g_H[(size_t)s * HDIM + j] * norm;
    atomicAdd(&g_A[(size_t)d * HDIM + j], v);
}

// ---------------------------------------------------------------------------
// Launch
// ---------------------------------------------------------------------------
extern "C" void kernel_launch(void* const* d_in, const int* in_sizes, int n_in,
                              void* d_out, int out_size) {
    const float* x  = (const float*)d_in[0];
    const int*   eidx = (const int*)d_in[1];   // int32 (JAX x64 disabled)
    const float* W1 = (const float*)d_in[2];
    const float* b1 = (const float*)d_in[3];
    const float* W2 = (const float*)d_in[4];
    const float* b2 = (const float*)d_in[5];
    const float* Wc = (const float*)d_in[6];
    const float* bc = (const float*)d_in[7];
    float* out = (float*)d_out;

    const int F_IN = 128;
    const int N = in_sizes[0] / F_IN;   // 50000
    const int E = in_sizes[1] / 2;      // 300000
    const int C = in_sizes[7];          // 32
    const int* src = eidx;
    const int* dst = eidx + E;

    // ---- degrees & normalization ----
    init_deg_kernel<<<(N + 255) / 256, 256>>>(N);
    deg_edges_kernel<<<(E + 255) / 256, 256>>>(dst, E);
    dinv_kernel<<<(N + 255) / 256, 256>>>(N);

    // ---- layer 1: g_H = X @ W1 ----
    {
        dim3 grid((N + 127) / 128, HDIM / 128);
        gemm1_kernel<<<grid, 256>>>(x, W1, N);
    }
    agg_init_kernel<<<N, HDIM>>>(b1, N);
    scatter_kernel<<<E, HDIM>>>(src, dst, E);

    // ---- layer 2: g_H = relu(g_A) @ W2 ----
    {
        dim3 grid((N + 127) / 128, HDIM / 128);
        gemm2_kernel<<<grid, 256>>>(W2, N);
    }
    agg_init_kernel<<<N, HDIM>>>(b2, N);
    scatter_kernel<<<E, HDIM>>>(src, dst, E);

    // ---- classifier: out = relu(g_A) @ Wc + bc ----
    {
        dim3 grid((N + 63) / 64, (C + 31) / 32);
        gemm3_kernel<<<grid, 256>>>(Wc, bc, out, N, C);
    }
    (void)n_in; (void)out_size;
}

// round 6
// speedup vs baseline: 1.9215x; 1.9215x over previous
#include <cuda_runtime.h>
#include <cuda_bf16.h>
#include <math.h>

// Problem constants: N=50000 nodes, F_IN=128, H=256, C=32.
#define MAXN 50000
#define HDIM 256

// Scratch (no allocations allowed). Referenced ONLY from device code.
__device__ float g_deg[MAXN];
__device__ float g_dinv[MAXN];
__device__ float g_H[MAXN * HDIM];   // GEMM output (messages source)
__device__ float g_A[MAXN * HDIM];   // aggregated output

// ---------------------------------------------------------------------------
// f32x2 packed-FMA helpers (sm_103a FFMA2 — only reachable via PTX)
// ---------------------------------------------------------------------------
__device__ __forceinline__ unsigned long long pack2(float x, float y) {
    unsigned long long r;
    asm("mov.b64 %0, {%1,%2};" : "=l"(r) : "f"(x), "f"(y));
    return r;
}
__device__ __forceinline__ void unpack2(unsigned long long v, float& x, float& y) {
    asm("mov.b64 {%0,%1}, %2;" : "=f"(x), "=f"(y) : "l"(v));
}
__device__ __forceinline__ void ffma2(unsigned long long& d,
                                      unsigned long long a,
                                      unsigned long long b) {
    asm("fma.rn.f32x2 %0, %1, %2, %0;" : "+l"(d) : "l"(a), "l"(b));
}

// ---------------------------------------------------------------------------
// Degree / normalization  (edge_index is int32)
// ---------------------------------------------------------------------------
__global__ void init_deg_kernel(int n) {
    int i = blockIdx.x * blockDim.x + threadIdx.x;
    if (i < n) g_deg[i] = 1.0f;
}
__global__ void deg_edges_kernel(const int* __restrict__ dst, int e) {
    int i = blockIdx.x * blockDim.x + threadIdx.x;
    if (i < e) atomicAdd(&g_deg[dst[i]], 1.0f);
}
__global__ void dinv_kernel(int n) {
    int i = blockIdx.x * blockDim.x + threadIdx.x;
    if (i < n) g_dinv[i] = rsqrtf(g_deg[i]);
}

// ---------------------------------------------------------------------------
// Main GEMM core: C[M, N] = op(A)[M,K] @ B[K,N], one 128x128 block per CTA.
// BM=128, BN=128, BK=16, 256 threads, TM=8, TN=8, double-buffered, FFMA2.
// ---------------------------------------------------------------------------
template <bool RELU>
__device__ __forceinline__ void gemm_main_core(const float* __restrict__ A,
                                               const float* __restrict__ B,
                                               float* __restrict__ C,
                                               int M, int K, int N) {
    constexpr int BM = 128, BN = 128, BK = 16;
    __shared__ float As[2][BM][BK + 4];
    __shared__ float Bs[2][BK][BN + 4];

    const int tid = threadIdx.x;
    const int tx = tid % 16;              // 16 col-groups of TN=8
    const int ty = tid / 16;              // 16 row-groups of TM=8
    const int row0 = blockIdx.x * BM;
    const int col0 = blockIdx.y * BN;

    // A tile: 128 rows x 16 k = 512 float4; 2 per thread.
    const int a_r0 = tid / 4;
    const int a_k4 = (tid % 4) * 4;
    // B tile: 16 rows x 128 cols = 512 float4; 2 per thread.
    const int b_r0 = tid / 32;
    const int b_c4 = (tid % 32) * 4;

    unsigned long long acc[8][4];
#pragma unroll
    for (int m = 0; m < 8; m++)
#pragma unroll
        for (int n = 0; n < 4; n++) acc[m][n] = pack2(0.0f, 0.0f);

    const int nt = K / BK;

    float4 va0, va1, vb0, vb1;
    auto ld_tiles = [&](int k0) {
        int gr0 = row0 + a_r0, gr1 = row0 + a_r0 + 64;
        float4 z = make_float4(0.f, 0.f, 0.f, 0.f);
        va0 = z; va1 = z;
        if (gr0 < M) va0 = *(const float4*)&A[(size_t)gr0 * K + k0 + a_k4];
        if (gr1 < M) va1 = *(const float4*)&A[(size_t)gr1 * K + k0 + a_k4];
        if (RELU) {
            va0.x = fmaxf(va0.x, 0.f); va0.y = fmaxf(va0.y, 0.f);
            va0.z = fmaxf(va0.z, 0.f); va0.w = fmaxf(va0.w, 0.f);
            va1.x = fmaxf(va1.x, 0.f); va1.y = fmaxf(va1.y, 0.f);
            va1.z = fmaxf(va1.z, 0.f); va1.w = fmaxf(va1.w, 0.f);
        }
        vb0 = *(const float4*)&B[(size_t)(k0 + b_r0) * N + col0 + b_c4];
        vb1 = *(const float4*)&B[(size_t)(k0 + b_r0 + 8) * N + col0 + b_c4];
    };
    auto st_tiles = [&](int buf) {
        *(float4*)&As[buf][a_r0][a_k4]      = va0;
        *(float4*)&As[buf][a_r0 + 64][a_k4] = va1;
        *(float4*)&Bs[buf][b_r0][b_c4]      = vb0;
        *(float4*)&Bs[buf][b_r0 + 8][b_c4]  = vb1;
    };

    ld_tiles(0);
    st_tiles(0);
    __syncthreads();

    for (int t = 0; t < nt; t++) {
        int cur = t & 1;
        bool more = (t + 1) < nt;
        if (more) ld_tiles((t + 1) * BK);

#pragma unroll
        for (int kk = 0; kk < BK; kk++) {
            const float2* bp = (const float2*)&Bs[cur][kk][tx * 8];
            unsigned long long rb[4];
#pragma unroll
            for (int n = 0; n < 4; n++) {
                float2 b2 = bp[n];
                rb[n] = pack2(b2.x, b2.y);
            }
#pragma unroll
            for (int m = 0; m < 8; m++) {
                float a = As[cur][ty * 8 + m][kk];
                unsigned long long am = pack2(a, a);
#pragma unroll
                for (int n = 0; n < 4; n++) ffma2(acc[m][n], am, rb[n]);
            }
        }

        if (more) st_tiles(cur ^ 1);
        __syncthreads();
    }

#pragma unroll
    for (int m = 0; m < 8; m++) {
        int gr = row0 + ty * 8 + m;
        if (gr >= M) continue;
        float v[8];
#pragma unroll
        for (int n = 0; n < 4; n++) unpack2(acc[m][n], v[2 * n], v[2 * n + 1]);
        float4 o0 = make_float4(v[0], v[1], v[2], v[3]);
        float4 o1 = make_float4(v[4], v[5], v[6], v[7]);
        float* cp = &C[(size_t)gr * N + col0 + tx * 8];
        *(float4*)cp = o0;
        *(float4*)(cp + 4) = o1;
    }
}

// Wrappers: scratch globals referenced from DEVICE code only.
__global__ void __launch_bounds__(256, 2)
gemm1_kernel(const float* __restrict__ x, const float* __restrict__ W1, int M) {
    gemm_main_core<false>(x, W1, g_H, M, 128, HDIM);
}
__global__ void __launch_bounds__(256, 2)
gemm2_kernel(const float* __restrict__ W2, int M) {
    gemm_main_core<true>(g_A, W2, g_H, M, HDIM, HDIM);
}

// ---------------------------------------------------------------------------
// Classifier GEMM: out[M,32] = relu(g_A)[M,256] @ Wc + bc
// ---------------------------------------------------------------------------
template <int BM, int BN, int BK, int TM, int TN>
__global__ void gemm_small(const float* __restrict__ B,
                           const float* __restrict__ bias,
                           float* __restrict__ C_, int M, int K, int N) {
    constexpr int THREADS = (BM / TM) * (BN / TN);
    __shared__ float As[BK][BM + 4];
    __shared__ float Bs[BK][BN + 4];

    const int tid = threadIdx.x;
    const int tx = tid % (BN / TN);
    const int ty = tid / (BN / TN);
    const int row0 = blockIdx.x * BM;
    const int col0 = blockIdx.y * BN;

    float acc[TM][TN];
#pragma unroll
    for (int m = 0; m < TM; m++)
#pragma unroll
        for (int n = 0; n < TN; n++) acc[m][n] = 0.0f;

    for (int k0 = 0; k0 < K; k0 += BK) {
#pragma unroll
        for (int i = tid; i < BM * BK; i += THREADS) {
            int r = i / BK, c = i % BK;
            int gr = row0 + r;
            float v = (gr < M) ? g_A[(size_t)gr * K + (k0 + c)] : 0.0f;
            As[c][r] = fmaxf(v, 0.0f);
        }
#pragma unroll
        for (int i = tid; i < BK * BN; i += THREADS) {
            int r = i / BN, c = i % BN;
            int gc = col0 + c;
            Bs[r][c] = (gc < N) ? B[(size_t)(k0 + r) * N + gc] : 0.0f;
        }
        __syncthreads();
#pragma unroll
        for (int kk = 0; kk < BK; kk++) {
            float ra[TM], rb[TN];
#pragma unroll
            for (int m = 0; m < TM; m++) ra[m] = As[kk][ty * TM + m];
#pragma unroll
            for (int n = 0; n < TN; n++) rb[n] = Bs[kk][tx * TN + n];
#pragma unroll
            for (int m = 0; m < TM; m++)
#pragma unroll
                for (int n = 0; n < TN; n++) acc[m][n] = fmaf(ra[m], rb[n], acc[m][n]);
        }
        __syncthreads();
    }
#pragma unroll
    for (int m = 0; m < TM; m++) {
        int gr = row0 + ty * TM + m;
        if (gr >= M) continue;
#pragma unroll
        for (int n = 0; n < TN; n++) {
            int gc = col0 + tx * TN + n;
            if (gc < N) C_[(size_t)gr * N + gc] = acc[m][n] + bias[gc];
        }
    }
}

// ---------------------------------------------------------------------------
// Aggregation init: g_A[i,:] = b[:] + dinv[i]^2 * g_H[i,:]  (float4, 64 thr)
// ---------------------------------------------------------------------------
__global__ void agg_init_kernel(const float* __restrict__ bias, int n) {
    int i = blockIdx.x;
    int j = threadIdx.x;                  // 0..63, 4 cols each
    if (i >= n) return;
    float di = g_dinv[i];
    float s = di * di;
    float4 h = *(const float4*)&g_H[(size_t)i * HDIM + j * 4];
    float4 b = *(const float4*)&bias[j * 4];
    float4 o = make_float4(b.x + s * h.x, b.y + s * h.y,
                           b.z + s * h.z, b.w + s * h.w);
    *(float4*)&g_A[(size_t)i * HDIM + j * 4] = o;
}

// ---------------------------------------------------------------------------
// Scatter: g_A[dst,:] += norm * g_H[src,:]. 4 edges/block, 64 lanes/edge,
// red.global.add.v4.f32 (no return → REDG path).
// ---------------------------------------------------------------------------
__global__ void scatter_kernel(const int* __restrict__ src,
                               const int* __restrict__ dst, int e) {
    int ed = blockIdx.x * 4 + threadIdx.x / 64;
    if (ed >= e) return;
    int lane = threadIdx.x % 64;
    int s = src[ed];
    int d = dst[ed];
    float norm = g_dinv[s] * g_dinv[d];
    float4 h = *(const float4*)&g_H[(size_t)s * HDIM + lane * 4];
    float4 v = make_float4(norm * h.x, norm * h.y, norm * h.z, norm * h.w);
    float* p = &g_A[(size_t)d * HDIM + lane * 4];
    asm volatile("red.global.add.v4.f32 [%0], {%1,%2,%3,%4};"
                 :: "l"(p), "f"(v.x), "f"(v.y), "f"(v.z), "f"(v.w)
                 : "memory");
}

// ---------------------------------------------------------------------------
// Launch
// ---------------------------------------------------------------------------
extern "C" void kernel_launch(void* const* d_in, const int* in_sizes, int n_in,
                              void* d_out, int out_size) {
    const float* x  = (const float*)d_in[0];
    const int* eidx = (const int*)d_in[1];
    const float* W1 = (const float*)d_in[2];
    const float* b1 = (const float*)d_in[3];
    const float* W2 = (const float*)d_in[4];
    const float* b2 = (const float*)d_in[5];
    const float* Wc = (const float*)d_in[6];
    const float* bc = (const float*)d_in[7];
    float* out = (float*)d_out;

    const int F_IN = 128;
    const int N = in_sizes[0] / F_IN;   // 50000
    const int E = in_sizes[1] / 2;      // 300000
    const int C = in_sizes[7];          // 32
    const int* src = eidx;
    const int* dst = eidx + E;

    init_deg_kernel<<<(N + 255) / 256, 256>>>(N);
    deg_edges_kernel<<<(E + 255) / 256, 256>>>(dst, E);
    dinv_kernel<<<(N + 255) / 256, 256>>>(N);

    // layer 1: g_H = X @ W1
    {
        dim3 grid((N + 127) / 128, HDIM / 128);
        gemm1_kernel<<<grid, 256>>>(x, W1, N);
    }
    agg_init_kernel<<<N, 64>>>(b1, N);
    scatter_kernel<<<(E + 3) / 4, 256>>>(src, dst, E);

    // layer 2: g_H = relu(g_A) @ W2
    {
        dim3 grid((N + 127) / 128, HDIM / 128);
        gemm2_kernel<<<grid, 256>>>(W2, N);
    }
    agg_init_kernel<<<N, 64>>>(b2, N);
    scatter_kernel<<<(E + 3) / 4, 256>>>(src, dst, E);

    // classifier
    {
        dim3 grid((N + 63) / 64, (C + 31) / 32);
        gemm_small<64, 32, 16, 4, 2><<<grid, 256>>>(Wc, bc, out, N, HDIM, C);
    }
    (void)n_in; (void)out_size;
}

// round 7
// speedup vs baseline: 2.0191x; 1.0508x over previous
#include <cuda_runtime.h>
#include <cuda_bf16.h>
#include <math.h>

// Problem constants: N=50000 nodes, F_IN=128, H=256, C=32.
#define MAXN 50000
#define HDIM 256

// Scratch (no allocations allowed). Referenced ONLY from device code.
__device__ float g_deg[MAXN];
__device__ float g_dinv[MAXN];
__device__ float g_H[MAXN * HDIM];   // GEMM output (messages source)
__device__ float g_A[MAXN * HDIM];   // aggregated output

// ---------------------------------------------------------------------------
// f32x2 packed-FMA helpers (sm_103a FFMA2 — only reachable via PTX)
// ---------------------------------------------------------------------------
__device__ __forceinline__ unsigned long long pack2(float x, float y) {
    unsigned long long r;
    asm("mov.b64 %0, {%1,%2};" : "=l"(r) : "f"(x), "f"(y));
    return r;
}
__device__ __forceinline__ void unpack2(unsigned long long v, float& x, float& y) {
    asm("mov.b64 {%0,%1}, %2;" : "=f"(x), "=f"(y) : "l"(v));
}
__device__ __forceinline__ void ffma2(unsigned long long& d,
                                      unsigned long long a,
                                      unsigned long long b) {
    asm("fma.rn.f32x2 %0, %1, %2, %0;" : "+l"(d) : "l"(a), "l"(b));
}

// ---------------------------------------------------------------------------
// Degree / normalization  (edge_index is int32)
// ---------------------------------------------------------------------------
__global__ void init_deg_kernel(int n) {
    int i = blockIdx.x * blockDim.x + threadIdx.x;
    if (i < n) g_deg[i] = 1.0f;
}
__global__ void deg_edges_kernel(const int* __restrict__ dst, int e) {
    int i = blockIdx.x * blockDim.x + threadIdx.x;
    if (i < e) atomicAdd(&g_deg[dst[i]], 1.0f);
}
__global__ void dinv_kernel(int n) {
    int i = blockIdx.x * blockDim.x + threadIdx.x;
    if (i < n) g_dinv[i] = rsqrtf(g_deg[i]);
}

// ---------------------------------------------------------------------------
// Main GEMM core: C[M,N] = op(A)[M,K] @ B[K,N], one 128x128 block per CTA.
// BM=128, BN=128, BK=16, 256 threads, TM=8, TN=8, double-buffered, FFMA2.
// As is k-major ([BK][BM+4]) so compute reads are 2x LDS.128 per operand.
// ---------------------------------------------------------------------------
template <bool RELU>
__device__ __forceinline__ void gemm_main_core(const float* __restrict__ A,
                                               const float* __restrict__ B,
                                               float* __restrict__ C,
                                               int M, int K, int N) {
    constexpr int BM = 128, BN = 128, BK = 16;
    __shared__ float As[2][BK][BM + 4];   // row stride 132 floats = 528 B (16B mult.)
    __shared__ float Bs[2][BK][BN + 4];

    const int tid = threadIdx.x;
    const int tx = tid % 16;              // 16 col-groups of TN=8
    const int ty = tid / 16;              // 16 row-groups of TM=8
    const int row0 = blockIdx.x * BM;
    const int col0 = blockIdx.y * BN;

    // A tile gmem mapping: 128 rows x 16 k = 512 float4; 2 per thread.
    const int a_r0 = tid / 4;
    const int a_k4 = (tid % 4) * 4;
    // B tile gmem mapping: 16 rows x 128 cols = 512 float4; 2 per thread.
    const int b_r0 = tid / 32;
    const int b_c4 = (tid % 32) * 4;

    unsigned long long acc[8][4];
#pragma unroll
    for (int m = 0; m < 8; m++)
#pragma unroll
        for (int n = 0; n < 4; n++) acc[m][n] = pack2(0.0f, 0.0f);

    const int nt = K / BK;

    float4 va0, va1, vb0, vb1;
    auto ld_tiles = [&](int k0) {
        int gr0 = row0 + a_r0, gr1 = row0 + a_r0 + 64;
        float4 z = make_float4(0.f, 0.f, 0.f, 0.f);
        va0 = z; va1 = z;
        if (gr0 < M) va0 = *(const float4*)&A[(size_t)gr0 * K + k0 + a_k4];
        if (gr1 < M) va1 = *(const float4*)&A[(size_t)gr1 * K + k0 + a_k4];
        if (RELU) {
            va0.x = fmaxf(va0.x, 0.f); va0.y = fmaxf(va0.y, 0.f);
            va0.z = fmaxf(va0.z, 0.f); va0.w = fmaxf(va0.w, 0.f);
            va1.x = fmaxf(va1.x, 0.f); va1.y = fmaxf(va1.y, 0.f);
            va1.z = fmaxf(va1.z, 0.f); va1.w = fmaxf(va1.w, 0.f);
        }
        vb0 = *(const float4*)&B[(size_t)(k0 + b_r0) * N + col0 + b_c4];
        vb1 = *(const float4*)&B[(size_t)(k0 + b_r0 + 8) * N + col0 + b_c4];
    };
    auto st_tiles = [&](int buf) {
        // A stored transposed (k-major): 4 scalar STS per float4, 2x per thread.
        As[buf][a_k4 + 0][a_r0] = va0.x;
        As[buf][a_k4 + 1][a_r0] = va0.y;
        As[buf][a_k4 + 2][a_r0] = va0.z;
        As[buf][a_k4 + 3][a_r0] = va0.w;
        As[buf][a_k4 + 0][a_r0 + 64] = va1.x;
        As[buf][a_k4 + 1][a_r0 + 64] = va1.y;
        As[buf][a_k4 + 2][a_r0 + 64] = va1.z;
        As[buf][a_k4 + 3][a_r0 + 64] = va1.w;
        *(float4*)&Bs[buf][b_r0][b_c4]     = vb0;
        *(float4*)&Bs[buf][b_r0 + 8][b_c4] = vb1;
    };

    ld_tiles(0);
    st_tiles(0);
    __syncthreads();

    for (int t = 0; t < nt; t++) {
        int cur = t & 1;
        bool more = (t + 1) < nt;
        if (more) ld_tiles((t + 1) * BK);

#pragma unroll
        for (int kk = 0; kk < BK; kk++) {
            float4 a0 = *(const float4*)&As[cur][kk][ty * 8];
            float4 a1 = *(const float4*)&As[cur][kk][ty * 8 + 4];
            float4 b0 = *(const float4*)&Bs[cur][kk][tx * 8];
            float4 b1 = *(const float4*)&Bs[cur][kk][tx * 8 + 4];
            unsigned long long rb[4];
            rb[0] = pack2(b0.x, b0.y);
            rb[1] = pack2(b0.z, b0.w);
            rb[2] = pack2(b1.x, b1.y);
            rb[3] = pack2(b1.z, b1.w);
            float am[8] = {a0.x, a0.y, a0.z, a0.w, a1.x, a1.y, a1.z, a1.w};
#pragma unroll
            for (int m = 0; m < 8; m++) {
                unsigned long long ap = pack2(am[m], am[m]);
#pragma unroll
                for (int n = 0; n < 4; n++) ffma2(acc[m][n], ap, rb[n]);
            }
        }

        if (more) st_tiles(cur ^ 1);
        __syncthreads();
    }

#pragma unroll
    for (int m = 0; m < 8; m++) {
        int gr = row0 + ty * 8 + m;
        if (gr >= M) continue;
        float v[8];
#pragma unroll
        for (int n = 0; n < 4; n++) unpack2(acc[m][n], v[2 * n], v[2 * n + 1]);
        float4 o0 = make_float4(v[0], v[1], v[2], v[3]);
        float4 o1 = make_float4(v[4], v[5], v[6], v[7]);
        float* cp = &C[(size_t)gr * N + col0 + tx * 8];
        *(float4*)cp = o0;
        *(float4*)(cp + 4) = o1;
    }
}

// Wrappers: scratch globals referenced from DEVICE code only.
__global__ void __launch_bounds__(256, 2)
gemm1_kernel(const float* __restrict__ x, const float* __restrict__ W1, int M) {
    gemm_main_core<false>(x, W1, g_H, M, 128, HDIM);
}
__global__ void __launch_bounds__(256, 2)
gemm2_kernel(const float* __restrict__ W2, int M) {
    gemm_main_core<true>(g_A, W2, g_H, M, HDIM, HDIM);
}

// ---------------------------------------------------------------------------
// Classifier GEMM: out[M,32] = relu(g_A)[M,256] @ Wc + bc
// ---------------------------------------------------------------------------
template <int BM, int BN, int BK, int TM, int TN>
__global__ void gemm_small(const float* __restrict__ B,
                           const float* __restrict__ bias,
                           float* __restrict__ C_, int M, int K, int N) {
    constexpr int THREADS = (BM / TM) * (BN / TN);
    __shared__ float As[BK][BM + 4];
    __shared__ float Bs[BK][BN + 4];

    const int tid = threadIdx.x;
    const int tx = tid % (BN / TN);
    const int ty = tid / (BN / TN);
    const int row0 = blockIdx.x * BM;
    const int col0 = blockIdx.y * BN;

    float acc[TM][TN];
#pragma unroll
    for (int m = 0; m < TM; m++)
#pragma unroll
        for (int n = 0; n < TN; n++) acc[m][n] = 0.0f;

    for (int k0 = 0; k0 < K; k0 += BK) {
#pragma unroll
        for (int i = tid; i < BM * BK; i += THREADS) {
            int r = i / BK, c = i % BK;
            int gr = row0 + r;
            float v = (gr < M) ? g_A[(size_t)gr * K + (k0 + c)] : 0.0f;
            As[c][r] = fmaxf(v, 0.0f);
        }
#pragma unroll
        for (int i = tid; i < BK * BN; i += THREADS) {
            int r = i / BN, c = i % BN;
            int gc = col0 + c;
            Bs[r][c] = (gc < N) ? B[(size_t)(k0 + r) * N + gc] : 0.0f;
        }
        __syncthreads();
#pragma unroll
        for (int kk = 0; kk < BK; kk++) {
            float ra[TM], rb[TN];
#pragma unroll
            for (int m = 0; m < TM; m++) ra[m] = As[kk][ty * TM + m];
#pragma unroll
            for (int n = 0; n < TN; n++) rb[n] = Bs[kk][tx * TN + n];
#pragma unroll
            for (int m = 0; m < TM; m++)
#pragma unroll
                for (int n = 0; n < TN; n++) acc[m][n] = fmaf(ra[m], rb[n], acc[m][n]);
        }
        __syncthreads();
    }
#pragma unroll
    for (int m = 0; m < TM; m++) {
        int gr = row0 + ty * TM + m;
        if (gr >= M) continue;
#pragma unroll
        for (int n = 0; n < TN; n++) {
            int gc = col0 + tx * TN + n;
            if (gc < N) C_[(size_t)gr * N + gc] = acc[m][n] + bias[gc];
        }
    }
}

// ---------------------------------------------------------------------------
// Aggregation init: g_A[i,:] = b[:] + dinv[i]^2 * g_H[i,:]  (float4, 64 thr)
// ---------------------------------------------------------------------------
__global__ void agg_init_kernel(const float* __restrict__ bias, int n) {
    int i = blockIdx.x;
    int j = threadIdx.x;                  // 0..63, 4 cols each
    if (i >= n) return;
    float di = g_dinv[i];
    float s = di * di;
    float4 h = *(const float4*)&g_H[(size_t)i * HDIM + j * 4];
    float4 b = *(const float4*)&bias[j * 4];
    float4 o = make_float4(b.x + s * h.x, b.y + s * h.y,
                           b.z + s * h.z, b.w + s * h.w);
    *(float4*)&g_A[(size_t)i * HDIM + j * 4] = o;
}

// ---------------------------------------------------------------------------
// Scatter: g_A[dst,:] += norm * g_H[src,:]. 4 edges/block, 64 lanes/edge,
// red.global.add.v4.f32 (no return → REDG path).
// ---------------------------------------------------------------------------
__global__ void scatter_kernel(const int* __restrict__ src,
                               const int* __restrict__ dst, int e) {
    int ed = blockIdx.x * 4 + threadIdx.x / 64;
    if (ed >= e) return;
    int lane = threadIdx.x % 64;
    int s = src[ed];
    int d = dst[ed];
    float norm = g_dinv[s] * g_dinv[d];
    float4 h = *(const float4*)&g_H[(size_t)s * HDIM + lane * 4];
    float4 v = make_float4(norm * h.x, norm * h.y, norm * h.z, norm * h.w);
    float* p = &g_A[(size_t)d * HDIM + lane * 4];
    asm volatile("red.global.add.v4.f32 [%0], {%1,%2,%3,%4};"
                 :: "l"(p), "f"(v.x), "f"(v.y), "f"(v.z), "f"(v.w)
                 : "memory");
}

// ---------------------------------------------------------------------------
// Launch
// ---------------------------------------------------------------------------
extern "C" void kernel_launch(void* const* d_in, const int* in_sizes, int n_in,
                              void* d_out, int out_size) {
    const float* x  = (const float*)d_in[0];
    const int* eidx = (const int*)d_in[1];
    const float* W1 = (const float*)d_in[2];
    const float* b1 = (const float*)d_in[3];
    const float* W2 = (const float*)d_in[4];
    const float* b2 = (const float*)d_in[5];
    const float* Wc = (const float*)d_in[6];
    const float* bc = (const float*)d_in[7];
    float* out = (float*)d_out;

    const int F_IN = 128;
    const int N = in_sizes[0] / F_IN;   // 50000
    const int E = in_sizes[1] / 2;      // 300000
    const int C = in_sizes[7];          // 32
    const int* src = eidx;
    const int* dst = eidx + E;

    init_deg_kernel<<<(N + 255) / 256, 256>>>(N);
    deg_edges_kernel<<<(E + 255) / 256, 256>>>(dst, E);
    dinv_kernel<<<(N + 255) / 256, 256>>>(N);

    // layer 1: g_H = X @ W1
    {
        dim3 grid((N + 127) / 128, HDIM / 128);
        gemm1_kernel<<<grid, 256>>>(x, W1, N);
    }
    agg_init_kernel<<<N, 64>>>(b1, N);
    scatter_kernel<<<(E + 3) / 4, 256>>>(src, dst, E);

    // layer 2: g_H = relu(g_A) @ W2
    {
        dim3 grid((N + 127) / 128, HDIM / 128);
        gemm2_kernel<<<grid, 256>>>(W2, N);
    }
    agg_init_kernel<<<N, 64>>>(b2, N);
    scatter_kernel<<<(E + 3) / 4, 256>>>(src, dst, E);

    // classifier
    {
        dim3 grid((N + 63) / 64, (C + 31) / 32);
        gemm_small<64, 32, 16, 4, 2><<<grid, 256>>>(Wc, bc, out, N, HDIM, C);
    }
    (void)n_in; (void)out_size;
}

// round 8
// speedup vs baseline: 2.2023x; 1.0907x over previous
#include <cuda_runtime.h>
#include <cuda_bf16.h>
#include <math.h>

// Problem constants: N=50000 nodes, F_IN=128, H=256, C=32.
#define MAXN 50000
#define HDIM 256

// Scratch (no allocations allowed). Referenced ONLY from device code.
__device__ float g_deg[MAXN];
__device__ float g_dinv[MAXN];
__device__ float g_H[MAXN * HDIM];    // GEMM output (messages source)
__device__ float g_A[MAXN * HDIM];    // layer-1 aggregate
__device__ float g_A2[MAXN * HDIM];   // layer-2 aggregate

// ---------------------------------------------------------------------------
// f32x2 packed-FMA helpers (sm_103a FFMA2 — only reachable via PTX)
// ---------------------------------------------------------------------------
__device__ __forceinline__ unsigned long long pack2(float x, float y) {
    unsigned long long r;
    asm("mov.b64 %0, {%1,%2};" : "=l"(r) : "f"(x), "f"(y));
    return r;
}
__device__ __forceinline__ void unpack2(unsigned long long v, float& x, float& y) {
    asm("mov.b64 {%0,%1}, %2;" : "=f"(x), "=f"(y) : "l"(v));
}
__device__ __forceinline__ void ffma2(unsigned long long& d,
                                      unsigned long long a,
                                      unsigned long long b) {
    asm("fma.rn.f32x2 %0, %1, %2, %0;" : "+l"(d) : "l"(a), "l"(b));
}

// ---------------------------------------------------------------------------
// Degree / normalization  (edge_index is int32)
// ---------------------------------------------------------------------------
__global__ void init_deg_kernel(int n) {
    int i = blockIdx.x * blockDim.x + threadIdx.x;
    if (i < n) g_deg[i] = 1.0f;
}
__global__ void deg_edges_kernel(const int* __restrict__ dst, int e) {
    int i = blockIdx.x * blockDim.x + threadIdx.x;
    if (i < e) atomicAdd(&g_deg[dst[i]], 1.0f);
}
__global__ void dinv_kernel(int n) {
    int i = blockIdx.x * blockDim.x + threadIdx.x;
    if (i < n) g_dinv[i] = rsqrtf(g_deg[i]);
}

// ---------------------------------------------------------------------------
// Main GEMM core + fused aggregation init.
//   C[M,N]    = op(A)[M,K] @ B[K,N]                (messages source g_H)
//   AOut[M,N] = bias[N] + dinv[row]^2 * C[row,:]   (self-loop + bias init)
// BM=128, BN=128, BK=16, 256 threads. Warp tile 64x32 (2x4 warps), lane 8x4,
// thread tile 8x8. k-major smem, double-buffered, FFMA2 inner loop.
// ---------------------------------------------------------------------------
template <bool RELU>
__device__ __forceinline__ void gemm_fused_core(const float* __restrict__ A,
                                                const float* __restrict__ B,
                                                const float* __restrict__ bias,
                                                float* __restrict__ C,
                                                float* __restrict__ AOut,
                                                int M, int K, int N) {
    constexpr int BM = 128, BN = 128, BK = 16;
    __shared__ float As[2][BK][BM + 4];
    __shared__ float Bs[2][BK][BN + 4];

    const int tid = threadIdx.x;
    const int warp = tid / 32, lane = tid % 32;
    const int warp_r = warp / 4, warp_c = warp % 4;   // 2 x 4 warps
    const int lane_r = lane / 4, lane_c = lane % 4;   // 8 x 4 lanes
    const int row_t = warp_r * 64 + lane_r * 8;       // thread's 8 rows
    const int col_t = warp_c * 32 + lane_c * 8;       // thread's 8 cols
    const int row0 = blockIdx.x * BM;
    const int col0 = blockIdx.y * BN;

    // A tile gmem mapping: 128 rows x 16 k = 512 float4; 2 per thread.
    const int a_r0 = tid / 4;
    const int a_k4 = (tid % 4) * 4;
    // B tile gmem mapping: 16 rows x 128 cols = 512 float4; 2 per thread.
    const int b_r0 = tid / 32;
    const int b_c4 = (tid % 32) * 4;

    unsigned long long acc[8][4];
#pragma unroll
    for (int m = 0; m < 8; m++)
#pragma unroll
        for (int n = 0; n < 4; n++) acc[m][n] = pack2(0.0f, 0.0f);

    const int nt = K / BK;

    float4 va0, va1, vb0, vb1;
    auto ld_tiles = [&](int k0) {
        int gr0 = row0 + a_r0, gr1 = row0 + a_r0 + 64;
        float4 z = make_float4(0.f, 0.f, 0.f, 0.f);
        va0 = z; va1 = z;
        if (gr0 < M) va0 = *(const float4*)&A[(size_t)gr0 * K + k0 + a_k4];
        if (gr1 < M) va1 = *(const float4*)&A[(size_t)gr1 * K + k0 + a_k4];
        if (RELU) {
            va0.x = fmaxf(va0.x, 0.f); va0.y = fmaxf(va0.y, 0.f);
            va0.z = fmaxf(va0.z, 0.f); va0.w = fmaxf(va0.w, 0.f);
            va1.x = fmaxf(va1.x, 0.f); va1.y = fmaxf(va1.y, 0.f);
            va1.z = fmaxf(va1.z, 0.f); va1.w = fmaxf(va1.w, 0.f);
        }
        vb0 = *(const float4*)&B[(size_t)(k0 + b_r0) * N + col0 + b_c4];
        vb1 = *(const float4*)&B[(size_t)(k0 + b_r0 + 8) * N + col0 + b_c4];
    };
    auto st_tiles = [&](int buf) {
        As[buf][a_k4 + 0][a_r0] = va0.x;
        As[buf][a_k4 + 1][a_r0] = va0.y;
        As[buf][a_k4 + 2][a_r0] = va0.z;
        As[buf][a_k4 + 3][a_r0] = va0.w;
        As[buf][a_k4 + 0][a_r0 + 64] = va1.x;
        As[buf][a_k4 + 1][a_r0 + 64] = va1.y;
        As[buf][a_k4 + 2][a_r0 + 64] = va1.z;
        As[buf][a_k4 + 3][a_r0 + 64] = va1.w;
        *(float4*)&Bs[buf][b_r0][b_c4]     = vb0;
        *(float4*)&Bs[buf][b_r0 + 8][b_c4] = vb1;
    };

    ld_tiles(0);
    st_tiles(0);
    __syncthreads();

    for (int t = 0; t < nt; t++) {
        int cur = t & 1;
        bool more = (t + 1) < nt;
        if (more) ld_tiles((t + 1) * BK);

#pragma unroll
        for (int kk = 0; kk < BK; kk++) {
            float4 a0 = *(const float4*)&As[cur][kk][row_t];
            float4 a1 = *(const float4*)&As[cur][kk][row_t + 4];
            float4 b0 = *(const float4*)&Bs[cur][kk][col_t];
            float4 b1 = *(const float4*)&Bs[cur][kk][col_t + 4];
            unsigned long long rb[4];
            rb[0] = pack2(b0.x, b0.y);
            rb[1] = pack2(b0.z, b0.w);
            rb[2] = pack2(b1.x, b1.y);
            rb[3] = pack2(b1.z, b1.w);
            float am[8] = {a0.x, a0.y, a0.z, a0.w, a1.x, a1.y, a1.z, a1.w};
#pragma unroll
            for (int m = 0; m < 8; m++) {
                unsigned long long ap = pack2(am[m], am[m]);
#pragma unroll
                for (int n = 0; n < 4; n++) ffma2(acc[m][n], ap, rb[n]);
            }
        }

        if (more) st_tiles(cur ^ 1);
        __syncthreads();
    }

    // Fused epilogue: C = acc;  AOut = bias + dinv^2 * acc.
    float4 bias0 = *(const float4*)&bias[col0 + col_t];
    float4 bias1 = *(const float4*)&bias[col0 + col_t + 4];
#pragma unroll
    for (int m = 0; m < 8; m++) {
        int gr = row0 + row_t + m;
        if (gr >= M) continue;
        float v[8];
#pragma unroll
        for (int n = 0; n < 4; n++) unpack2(acc[m][n], v[2 * n], v[2 * n + 1]);
        float4 o0 = make_float4(v[0], v[1], v[2], v[3]);
        float4 o1 = make_float4(v[4], v[5], v[6], v[7]);
        size_t off = (size_t)gr * N + col0 + col_t;
        *(float4*)&C[off]     = o0;
        *(float4*)&C[off + 4] = o1;
        float di = g_dinv[gr];
        float s = di * di;
        float4 w0 = make_float4(bias0.x + s * o0.x, bias0.y + s * o0.y,
                                bias0.z + s * o0.z, bias0.w + s * o0.w);
        float4 w1 = make_float4(bias1.x + s * o1.x, bias1.y + s * o1.y,
                                bias1.z + s * o1.z, bias1.w + s * o1.w);
        *(float4*)&AOut[off]     = w0;
        *(float4*)&AOut[off + 4] = w1;
    }
}

// Wrappers: scratch globals referenced from DEVICE code only.
__global__ void __launch_bounds__(256, 2)
gemm1_kernel(const float* __restrict__ x, const float* __restrict__ W1,
             const float* __restrict__ b1, int M) {
    gemm_fused_core<false>(x, W1, b1, g_H, g_A, M, 128, HDIM);
}
__global__ void __launch_bounds__(256, 2)
gemm2_kernel(const float* __restrict__ W2, const float* __restrict__ b2, int M) {
    gemm_fused_core<true>(g_A, W2, b2, g_H, g_A2, M, HDIM, HDIM);
}

// ---------------------------------------------------------------------------
// Classifier GEMM: out[M,32] = relu(g_A2)[M,256] @ Wc + bc
// ---------------------------------------------------------------------------
template <int BM, int BN, int BK, int TM, int TN>
__global__ void gemm_small(const float* __restrict__ B,
                           const float* __restrict__ bias,
                           float* __restrict__ C_, int M, int K, int N) {
    constexpr int THREADS = (BM / TM) * (BN / TN);
    __shared__ float As[BK][BM + 4];
    __shared__ float Bs[BK][BN + 4];

    const int tid = threadIdx.x;
    const int tx = tid % (BN / TN);
    const int ty = tid / (BN / TN);
    const int row0 = blockIdx.x * BM;
    const int col0 = blockIdx.y * BN;

    float acc[TM][TN];
#pragma unroll
    for (int m = 0; m < TM; m++)
#pragma unroll
        for (int n = 0; n < TN; n++) acc[m][n] = 0.0f;

    for (int k0 = 0; k0 < K; k0 += BK) {
#pragma unroll
        for (int i = tid; i < BM * BK; i += THREADS) {
            int r = i / BK, c = i % BK;
            int gr = row0 + r;
            float v = (gr < M) ? g_A2[(size_t)gr * K + (k0 + c)] : 0.0f;
            As[c][r] = fmaxf(v, 0.0f);
        }
#pragma unroll
        for (int i = tid; i < BK * BN; i += THREADS) {
            int r = i / BN, c = i % BN;
            int gc = col0 + c;
            Bs[r][c] = (gc < N) ? B[(size_t)(k0 + r) * N + gc] : 0.0f;
        }
        __syncthreads();
#pragma unroll
        for (int kk = 0; kk < BK; kk++) {
            float ra[TM], rb[TN];
#pragma unroll
            for (int m = 0; m < TM; m++) ra[m] = As[kk][ty * TM + m];
#pragma unroll
            for (int n = 0; n < TN; n++) rb[n] = Bs[kk][tx * TN + n];
#pragma unroll
            for (int m = 0; m < TM; m++)
#pragma unroll
                for (int n = 0; n < TN; n++) acc[m][n] = fmaf(ra[m], rb[n], acc[m][n]);
        }
        __syncthreads();
    }
#pragma unroll
    for (int m = 0; m < TM; m++) {
        int gr = row0 + ty * TM + m;
        if (gr >= M) continue;
#pragma unroll
        for (int n = 0; n < TN; n++) {
            int gc = col0 + tx * TN + n;
            if (gc < N) C_[(size_t)gr * N + gc] = acc[m][n] + bias[gc];
        }
    }
}

// ---------------------------------------------------------------------------
// Scatter: target[dst,:] += norm * g_H[src,:]. 4 edges/block, 64 lanes/edge,
// red.global.add.v4.f32 (REDG path). Target buffer selected device-side.
// ---------------------------------------------------------------------------
__global__ void scatter_kernel(const int* __restrict__ src,
                               const int* __restrict__ dst, int e, int which) {
    int ed = blockIdx.x * 4 + threadIdx.x / 64;
    if (ed >= e) return;
    int lane = threadIdx.x % 64;
    int s = src[ed];
    int d = dst[ed];
    float norm = g_dinv[s] * g_dinv[d];
    float4 h = *(const float4*)&g_H[(size_t)s * HDIM + lane * 4];
    float4 v = make_float4(norm * h.x, norm * h.y, norm * h.z, norm * h.w);
    float* base = which ? g_A2 : g_A;
    float* p = &base[(size_t)d * HDIM + lane * 4];
    asm volatile("red.global.add.v4.f32 [%0], {%1,%2,%3,%4};"
                 :: "l"(p), "f"(v.x), "f"(v.y), "f"(v.z), "f"(v.w)
                 : "memory");
}

// ---------------------------------------------------------------------------
// Launch
// ---------------------------------------------------------------------------
extern "C" void kernel_launch(void* const* d_in, const int* in_sizes, int n_in,
                              void* d_out, int out_size) {
    const float* x  = (const float*)d_in[0];
    const int* eidx = (const int*)d_in[1];
    const float* W1 = (const float*)d_in[2];
    const float* b1 = (const float*)d_in[3];
    const float* W2 = (const float*)d_in[4];
    const float* b2 = (const float*)d_in[5];
    const float* Wc = (const float*)d_in[6];
    const float* bc = (const float*)d_in[7];
    float* out = (float*)d_out;

    const int F_IN = 128;
    const int N = in_sizes[0] / F_IN;   // 50000
    const int E = in_sizes[1] / 2;      // 300000
    const int C = in_sizes[7];          // 32
    const int* src = eidx;
    const int* dst = eidx + E;

    init_deg_kernel<<<(N + 255) / 256, 256>>>(N);
    deg_edges_kernel<<<(E + 255) / 256, 256>>>(dst, E);
    dinv_kernel<<<(N + 255) / 256, 256>>>(N);

    // layer 1: g_H = X @ W1 ; g_A = b1 + dinv^2*g_H (fused)
    {
        dim3 grid((N + 127) / 128, HDIM / 128);
        gemm1_kernel<<<grid, 256>>>(x, W1, b1, N);
    }
    scatter_kernel<<<(E + 3) / 4, 256>>>(src, dst, E, 0);

    // layer 2: g_H = relu(g_A) @ W2 ; g_A2 = b2 + dinv^2*g_H (fused)
    {
        dim3 grid((N + 127) / 128, HDIM / 128);
        gemm2_kernel<<<grid, 256>>>(W2, b2, N);
    }
    scatter_kernel<<<(E + 3) / 4, 256>>>(src, dst, E, 1);

    // classifier: out = relu(g_A2) @ Wc + bc
    {
        dim3 grid((N + 63) / 64, (C + 31) / 32);
        gemm_small<64, 32, 16, 4, 2><<<grid, 256>>>(Wc, bc, out, N, HDIM, C);
    }
    (void)n_in; (void)out_size;
}

// round 10
// speedup vs baseline: 2.9318x; 1.3312x over previous
#include <cuda_runtime.h>
#include <cuda_bf16.h>
#include <math.h>
#include <stdint.h>

// Problem constants: N=50000 nodes, F_IN=128, H=256, C=32.
#define MAXN 50000
#define HDIM 256

// Scratch (no allocations allowed). Referenced ONLY from device code.
__device__ float g_deg[MAXN];
__device__ float g_dinv[MAXN];
__device__ float g_H[MAXN * HDIM];    // GEMM output (messages source)
__device__ float g_A[MAXN * HDIM];    // layer-1 aggregate
__device__ float g_A2[MAXN * HDIM];   // layer-2 aggregate
__device__ float g_WT[HDIM * HDIM];   // transposed weights [n][k]

// ---------------------------------------------------------------------------
// Helpers
// ---------------------------------------------------------------------------
__device__ __forceinline__ uint32_t smem_u32(const void* p) {
    uint32_t a;
    asm("{ .reg .u64 t; cvta.to.shared.u64 t, %1; cvt.u32.u64 %0, t; }"
        : "=r"(a) : "l"(p));
    return a;
}
__device__ __forceinline__ uint32_t to_tf32(float x) {
    float r;
    asm("cvt.rna.tf32.f32 %0, %1;" : "=f"(r) : "f"(x));
    return __float_as_uint(r);
}
__device__ __forceinline__ void ldsm_x4(uint32_t& r0, uint32_t& r1,
                                        uint32_t& r2, uint32_t& r3,
                                        uint32_t addr) {
    asm volatile("ldmatrix.sync.aligned.m8n8.x4.shared.b16 {%0,%1,%2,%3}, [%4];"
                 : "=r"(r0), "=r"(r1), "=r"(r2), "=r"(r3) : "r"(addr));
}
__device__ __forceinline__ void mma_tf32(float* d, const uint32_t* a,
                                         const uint32_t* b) {
    asm volatile(
        "mma.sync.aligned.m16n8k8.row.col.f32.tf32.tf32.f32 "
        "{%0,%1,%2,%3}, {%4,%5,%6,%7}, {%8,%9}, {%0,%1,%2,%3};"
        : "+f"(d[0]), "+f"(d[1]), "+f"(d[2]), "+f"(d[3])
        : "r"(a[0]), "r"(a[1]), "r"(a[2]), "r"(a[3]), "r"(b[0]), "r"(b[1]));
}

// ---------------------------------------------------------------------------
// Degree / normalization  (edge_index is int32)
// ---------------------------------------------------------------------------
__global__ void init_deg_kernel(int n) {
    int i = blockIdx.x * blockDim.x + threadIdx.x;
    if (i < n) g_deg[i] = 1.0f;
}
__global__ void deg_edges_kernel(const int* __restrict__ dst, int e) {
    int i = blockIdx.x * blockDim.x + threadIdx.x;
    if (i < e) atomicAdd(&g_deg[dst[i]], 1.0f);
}
__global__ void dinv_kernel(int n) {
    int i = blockIdx.x * blockDim.x + threadIdx.x;
    if (i < n) g_dinv[i] = rsqrtf(g_deg[i]);
}

// ---------------------------------------------------------------------------
// Weight transpose: g_WT[n][k] = W[k][n].  W is [K][HDIM].
// ---------------------------------------------------------------------------
__global__ void wtrans_kernel(const float* __restrict__ W, int K) {
    __shared__ float t[32][33];
    int k0 = blockIdx.x * 32, n0 = blockIdx.y * 32;
    int tx = threadIdx.x, ty = threadIdx.y;           // 32 x 8
#pragma unroll
    for (int j = 0; j < 32; j += 8) {
        int k = k0 + ty + j, n = n0 + tx;
        t[ty + j][tx] = (k < K) ? W[(size_t)k * HDIM + n] : 0.0f;
    }
    __syncthreads();
#pragma unroll
    for (int j = 0; j < 32; j += 8) {
        int n = n0 + ty + j, k = k0 + tx;
        if (k < K) g_WT[(size_t)n * K + k] = t[tx][ty + j];
    }
}

// ---------------------------------------------------------------------------
// TF32 mma.sync GEMM + fused aggregation epilogue.
//   g_H[M,256]  = op(A)[M,K] @ W[K,256]   (B from g_WT, K-major [n][k])
//   AOut[M,256] = bias + dinv[row]^2 * g_H[row,:]
// CTA = 128 rows x 128 cols, BK=16, 256 threads (8 warps as 2x4, 64x32/warp).
// Smem rows are 16 floats (64B) with XOR swizzle off^=((off>>3)&0x30),
// conflict-free for both float4 stores and ldmatrix reads.
// ---------------------------------------------------------------------------
template <int K, bool RELU, int SEL>
__global__ void __launch_bounds__(256)
gemm_mma(const float* __restrict__ Ain, const float* __restrict__ bias, int M) {
    const float* A = (SEL == 0) ? Ain : g_A;
    float* Cout = g_H;
    float* AOut = (SEL == 0) ? g_A : g_A2;

    __shared__ float As[2][128 * 16];
    __shared__ float Bs[2][128 * 16];

    const int tid = threadIdx.x;
    const int wid = tid >> 5, lane = tid & 31;
    const int warp_m = wid >> 2, warp_n = wid & 3;
    const int row0 = blockIdx.x * 128;
    const int col0 = blockIdx.y * 128;

    const uint32_t baseA = smem_u32(As);
    const uint32_t baseB = smem_u32(Bs);

    // ---- gmem -> reg staging (double buffer) ----
    uint4 ra[2], rb[2];
    auto ld_g = [&](int t) {
#pragma unroll
        for (int j = 0; j < 2; j++) {
            int idx = j * 256 + tid;
            int r = idx >> 2, c = idx & 3;
            int gr = row0 + r;
            float4 v = make_float4(0.f, 0.f, 0.f, 0.f);
            if (gr < M) v = *(const float4*)&A[(size_t)gr * K + t * 16 + c * 4];
            if (RELU) {
                v.x = fmaxf(v.x, 0.f); v.y = fmaxf(v.y, 0.f);
                v.z = fmaxf(v.z, 0.f); v.w = fmaxf(v.w, 0.f);
            }
            ra[j].x = to_tf32(v.x); ra[j].y = to_tf32(v.y);
            ra[j].z = to_tf32(v.z); ra[j].w = to_tf32(v.w);
            float4 w = *(const float4*)&g_WT[(size_t)(col0 + r) * K + t * 16 + c * 4];
            rb[j].x = to_tf32(w.x); rb[j].y = to_tf32(w.y);
            rb[j].z = to_tf32(w.z); rb[j].w = to_tf32(w.w);
        }
    };
    auto st_s = [&](int b) {
#pragma unroll
        for (int j = 0; j < 2; j++) {
            int idx = j * 256 + tid;
            int r = idx >> 2, c = idx & 3;
            uint32_t off = (uint32_t)(r * 64 + ((c ^ ((r >> 1) & 3)) << 4));
            *(uint4*)((char*)As[b] + off) = ra[j];
            *(uint4*)((char*)Bs[b] + off) = rb[j];
        }
    };

    // ---- ldmatrix address precompute ----
    // A frag mi: matrices (m_id): 0: rows+0-7 kc=2s, 1: rows+8-15 kc=2s,
    //                             2: rows+0-7 kc=2s+1, 3: rows+8-15 kc=2s+1
    uint32_t a_row[4], a_sw[4];
#pragma unroll
    for (int mi = 0; mi < 4; mi++) {
        int row = warp_m * 64 + mi * 16 + ((lane >> 3) & 1) * 8 + (lane & 7);
        a_row[mi] = (uint32_t)(row * 64);
        a_sw[mi] = (uint32_t)((row >> 1) & 3);
    }
    const uint32_t a_chi = (uint32_t)((lane >> 4) & 1);   // chunk half
    // B frag pair njp: matrices: 0: n+0-7 kc=2s, 1: n+0-7 kc=2s+1,
    //                            2: n+8-15 kc=2s, 3: n+8-15 kc=2s+1
    uint32_t b_row[2], b_sw[2];
#pragma unroll
    for (int njp = 0; njp < 2; njp++) {
        int n = warp_n * 32 + njp * 16 + ((lane >> 4) & 1) * 8 + (lane & 7);
        b_row[njp] = (uint32_t)(n * 64);
        b_sw[njp] = (uint32_t)((n >> 1) & 3);
    }
    const uint32_t b_chi = (uint32_t)((lane >> 3) & 1);

    float acc[4][4][4];
#pragma unroll
    for (int mi = 0; mi < 4; mi++)
#pragma unroll
        for (int nj = 0; nj < 4; nj++)
#pragma unroll
            for (int i = 0; i < 4; i++) acc[mi][nj][i] = 0.0f;

    constexpr int NT = K / 16;

    ld_g(0);
    st_s(0);
    __syncthreads();

    for (int t = 0; t < NT; t++) {
        int cur = t & 1;
        bool more = (t + 1) < NT;
        if (more) ld_g(t + 1);

        uint32_t bA = baseA + (uint32_t)cur * 8192;
        uint32_t bB = baseB + (uint32_t)cur * 8192;
#pragma unroll
        for (int s = 0; s < 2; s++) {
            uint32_t af[4][4];
#pragma unroll
            for (int mi = 0; mi < 4; mi++) {
                uint32_t ch = 2 * s + a_chi;
                uint32_t addr = bA + a_row[mi] + ((ch ^ a_sw[mi]) << 4);
                ldsm_x4(af[mi][0], af[mi][1], af[mi][2], af[mi][3], addr);
            }
            uint32_t bf[4][2];
#pragma unroll
            for (int njp = 0; njp < 2; njp++) {
                uint32_t ch = 2 * s + b_chi;
                uint32_t addr = bB + b_row[njp] + ((ch ^ b_sw[njp]) << 4);
                uint32_t r0, r1, r2, r3;
                ldsm_x4(r0, r1, r2, r3, addr);
                bf[2 * njp][0] = r0;     bf[2 * njp][1] = r1;
                bf[2 * njp + 1][0] = r2; bf[2 * njp + 1][1] = r3;
            }
#pragma unroll
            for (int mi = 0; mi < 4; mi++)
#pragma unroll
                for (int nj = 0; nj < 4; nj++)
                    mma_tf32(acc[mi][nj], af[mi], bf[nj]);
        }

        if (more) st_s(cur ^ 1);
        __syncthreads();
    }

    // ---- fused epilogue ----
    const int g = lane >> 2, tg = lane & 3;
#pragma unroll
    for (int mi = 0; mi < 4; mi++) {
        int R0 = row0 + warp_m * 64 + mi * 16 + g;
        int R1 = R0 + 8;
        float d0 = (R0 < M) ? g_dinv[R0] : 0.0f;
        float d1 = (R1 < M) ? g_dinv[R1] : 0.0f;
        float s0 = d0 * d0, s1 = d1 * d1;
#pragma unroll
        for (int nj = 0; nj < 4; nj++) {
            int cc = col0 + warp_n * 32 + nj * 8 + tg * 2;
            float2 bb = *(const float2*)&bias[cc];
            if (R0 < M) {
                size_t o = (size_t)R0 * HDIM + cc;
                *(float2*)&Cout[o] = make_float2(acc[mi][nj][0], acc[mi][nj][1]);
                *(float2*)&AOut[o] = make_float2(bb.x + s0 * acc[mi][nj][0],
                                                 bb.y + s0 * acc[mi][nj][1]);
            }
            if (R1 < M) {
                size_t o = (size_t)R1 * HDIM + cc;
                *(float2*)&Cout[o] = make_float2(acc[mi][nj][2], acc[mi][nj][3]);
                *(float2*)&AOut[o] = make_float2(bb.x + s1 * acc[mi][nj][2],
                                                 bb.y + s1 * acc[mi][nj][3]);
            }
        }
    }
}

// ---------------------------------------------------------------------------
// Classifier GEMM: out[M,32] = relu(g_A2)[M,256] @ Wc + bc  (exact fp32)
// ---------------------------------------------------------------------------
template <int BM, int BN, int BK, int TM, int TN>
__global__ void gemm_small(const float* __restrict__ B,
                           const float* __restrict__ bias,
                           float* __restrict__ C_, int M, int K, int N) {
    constexpr int THREADS = (BM / TM) * (BN / TN);
    __shared__ float As[BK][BM + 4];
    __shared__ float Bs[BK][BN + 4];

    const int tid = threadIdx.x;
    const int tx = tid % (BN / TN);
    const int ty = tid / (BN / TN);
    const int row0 = blockIdx.x * BM;
    const int col0 = blockIdx.y * BN;

    float acc[TM][TN];
#pragma unroll
    for (int m = 0; m < TM; m++)
#pragma unroll
        for (int n = 0; n < TN; n++) acc[m][n] = 0.0f;

    for (int k0 = 0; k0 < K; k0 += BK) {
#pragma unroll
        for (int i = tid; i < BM * BK; i += THREADS) {
            int r = i / BK, c = i % BK;
            int gr = row0 + r;
            float v = (gr < M) ? g_A2[(size_t)gr * K + (k0 + c)] : 0.0f;
            As[c][r] = fmaxf(v, 0.0f);
        }
#pragma unroll
        for (int i = tid; i < BK * BN; i += THREADS) {
            int r = i / BN, c = i % BN;
            int gc = col0 + c;
            Bs[r][c] = (gc < N) ? B[(size_t)(k0 + r) * N + gc] : 0.0f;
        }
        __syncthreads();
#pragma unroll
        for (int kk = 0; kk < BK; kk++) {
            float ra[TM], rb[TN];
#pragma unroll
            for (int m = 0; m < TM; m++) ra[m] = As[kk][ty * TM + m];
#pragma unroll
            for (int n = 0; n < TN; n++) rb[n] = Bs[kk][tx * TN + n];
#pragma unroll
            for (int m = 0; m < TM; m++)
#pragma unroll
                for (int n = 0; n < TN; n++) acc[m][n] = fmaf(ra[m], rb[n], acc[m][n]);
        }
        __syncthreads();
    }
#pragma unroll
    for (int m = 0; m < TM; m++) {
        int gr = row0 + ty * TM + m;
        if (gr >= M) continue;
#pragma unroll
        for (int n = 0; n < TN; n++) {
            int gc = col0 + tx * TN + n;
            if (gc < N) C_[(size_t)gr * N + gc] = acc[m][n] + bias[gc];
        }
    }
}

// ---------------------------------------------------------------------------
// Scatter: target[dst,:] += norm * g_H[src,:]. 4 edges/block, 64 lanes/edge,
// red.global.add.v4.f32 (REDG path). Target buffer selected device-side.
// ---------------------------------------------------------------------------
__global__ void scatter_kernel(const int* __restrict__ src,
                               const int* __restrict__ dst, int e, int which) {
    int ed = blockIdx.x * 4 + threadIdx.x / 64;
    if (ed >= e) return;
    int lane = threadIdx.x % 64;
    int s = src[ed];
    int d = dst[ed];
    float norm = g_dinv[s] * g_dinv[d];
    float4 h = *(const float4*)&g_H[(size_t)s * HDIM + lane * 4];
    float4 v = make_float4(norm * h.x, norm * h.y, norm * h.z, norm * h.w);
    float* base = which ? g_A2 : g_A;
    float* p = &base[(size_t)d * HDIM + lane * 4];
    asm volatile("red.global.add.v4.f32 [%0], {%1,%2,%3,%4};"
                 :: "l"(p), "f"(v.x), "f"(v.y), "f"(v.z), "f"(v.w)
                 : "memory");
}

// ---------------------------------------------------------------------------
// Launch
// ---------------------------------------------------------------------------
extern "C" void kernel_launch(void* const* d_in, const int* in_sizes, int n_in,
                              void* d_out, int out_size) {
    const float* x  = (const float*)d_in[0];
    const int* eidx = (const int*)d_in[1];
    const float* W1 = (const float*)d_in[2];
    const float* b1 = (const float*)d_in[3];
    const float* W2 = (const float*)d_in[4];
    const float* b2 = (const float*)d_in[5];
    const float* Wc = (const float*)d_in[6];
    const float* bc = (const float*)d_in[7];
    float* out = (float*)d_out;

    const int F_IN = 128;
    const int N = in_sizes[0] / F_IN;   // 50000
    const int E = in_sizes[1] / 2;      // 300000
    const int C = in_sizes[7];          // 32
    const int* src = eidx;
    const int* dst = eidx + E;

    init_deg_kernel<<<(N + 255) / 256, 256>>>(N);
    deg_edges_kernel<<<(E + 255) / 256, 256>>>(dst, E);
    dinv_kernel<<<(N + 255) / 256, 256>>>(N);

    const int RB = (N + 127) / 128;     // 391 row blocks
    dim3 ggrid(RB, HDIM / 128);         // 391 x 2

    // layer 1: g_H = X @ W1 ; g_A = b1 + dinv^2*g_H (fused)
    wtrans_kernel<<<dim3(F_IN / 32, HDIM / 32), dim3(32, 8)>>>(W1, F_IN);
    gemm_mma<128, false, 0><<<ggrid, 256>>>(x, b1, N);
    scatter_kernel<<<(E + 3) / 4, 256>>>(src, dst, E, 0);

    // layer 2: g_H = relu(g_A) @ W2 ; g_A2 = b2 + dinv^2*g_H (fused)
    wtrans_kernel<<<dim3(HDIM / 32, HDIM / 32), dim3(32, 8)>>>(W2, HDIM);
    gemm_mma<256, true, 1><<<ggrid, 256>>>(nullptr, b2, N);
    scatter_kernel<<<(E + 3) / 4, 256>>>(src, dst, E, 1);

    // classifier: out = relu(g_A2) @ Wc + bc (exact fp32)
    {
        dim3 grid((N + 63) / 64, (C + 31) / 32);
        gemm_small<64, 32, 16, 4, 2><<<grid, 256>>>(Wc, bc, out, N, HDIM, C);
    }
    (void)n_in; (void)out_size;
}

// round 12
// speedup vs baseline: 3.0725x; 1.0480x over previous
#include <cuda_runtime.h>
#include <cuda_bf16.h>
#include <math.h>
#include <stdint.h>

// Problem constants: N=50000 nodes, E=300000 edges, F_IN=128, H=256, C=32.
#define MAXN 50000
#define MAXE 300000
#define HDIM 256

// Scratch (no allocations allowed). Referenced ONLY from device code.
__device__ float g_dinv[MAXN];
__device__ int   g_cnt[MAXN];
__device__ int   g_pos[MAXN];
__device__ int   g_rowptr[MAXN + 1];
__device__ int   g_srcs[MAXE];
__device__ float g_H[MAXN * HDIM];    // GEMM output (messages source)
__device__ float g_A[MAXN * HDIM];    // layer-1 aggregate
__device__ float g_A2[MAXN * HDIM];   // layer-2 aggregate
__device__ float g_WT[HDIM * HDIM];   // transposed weights [n][k]

// ---------------------------------------------------------------------------
// Helpers
// ---------------------------------------------------------------------------
__device__ __forceinline__ uint32_t smem_u32(const void* p) {
    uint32_t a;
    asm("{ .reg .u64 t; cvta.to.shared.u64 t, %1; cvt.u32.u64 %0, t; }"
        : "=r"(a) : "l"(p));
    return a;
}
__device__ __forceinline__ uint32_t to_tf32(float x) {
    float r;
    asm("cvt.rna.tf32.f32 %0, %1;" : "=f"(r) : "f"(x));
    return __float_as_uint(r);
}
__device__ __forceinline__ void ldsm_x4(uint32_t& r0, uint32_t& r1,
                                        uint32_t& r2, uint32_t& r3,
                                        uint32_t addr) {
    asm volatile("ldmatrix.sync.aligned.m8n8.x4.shared.b16 {%0,%1,%2,%3}, [%4];"
                 : "=r"(r0), "=r"(r1), "=r"(r2), "=r"(r3) : "r"(addr));
}
__device__ __forceinline__ void mma_tf32(float* d, const uint32_t* a,
                                         const uint32_t* b) {
    asm volatile(
        "mma.sync.aligned.m16n8k8.row.col.f32.tf32.tf32.f32 "
        "{%0,%1,%2,%3}, {%4,%5,%6,%7}, {%8,%9}, {%0,%1,%2,%3};"
        : "+f"(d[0]), "+f"(d[1]), "+f"(d[2]), "+f"(d[3])
        : "r"(a[0]), "r"(a[1]), "r"(a[2]), "r"(a[3]), "r"(b[0]), "r"(b[1]));
}

// ---------------------------------------------------------------------------
// CSR build (dst-major) + dinv
// ---------------------------------------------------------------------------
__global__ void zero_cnt_kernel(int n) {
    int i = blockIdx.x * blockDim.x + threadIdx.x;
    if (i < n) { g_cnt[i] = 0; g_pos[i] = 0; }
}
__global__ void count_kernel(const int* __restrict__ dst, int e) {
    int i = blockIdx.x * blockDim.x + threadIdx.x;
    if (i < e) atomicAdd(&g_cnt[dst[i]], 1);
}
// Single-CTA scan: 1024 threads, each owns a contiguous chunk.
__global__ void scan_kernel(int n, int e) {
    __shared__ int part[1024];
    const int t = threadIdx.x;
    const int per = (n + 1023) / 1024;
    const int start = t * per;
    int sum = 0;
    for (int i = 0; i < per; i++) {
        int idx = start + i;
        if (idx < n) { g_rowptr[idx] = sum; sum += g_cnt[idx]; }
    }
    part[t] = sum;
    __syncthreads();
    for (int off = 1; off < 1024; off <<= 1) {
        int v = (t >= off) ? part[t - off] : 0;
        __syncthreads();
        part[t] += v;
        __syncthreads();
    }
    int offset = (t > 0) ? part[t - 1] : 0;
    for (int i = 0; i < per; i++) {
        int idx = start + i;
        if (idx < n) g_rowptr[idx] += offset;
    }
    if (t == 0) g_rowptr[n] = e;
    for (int i = t; i < n; i += 1024)
        g_dinv[i] = rsqrtf((float)g_cnt[i] + 1.0f);   // +1 self-loop
}
__global__ void fill_kernel(const int* __restrict__ src,
                            const int* __restrict__ dst, int e) {
    int i = blockIdx.x * blockDim.x + threadIdx.x;
    if (i < e) {
        int d = dst[i];
        int p = atomicAdd(&g_pos[d], 1);
        g_srcs[g_rowptr[d] + p] = src[i];
    }
}

// ---------------------------------------------------------------------------
// Weight transpose: g_WT[n][k] = W[k][n].  W is [K][HDIM].
// ---------------------------------------------------------------------------
__global__ void wtrans_kernel(const float* __restrict__ W, int K) {
    __shared__ float t[32][33];
    int k0 = blockIdx.x * 32, n0 = blockIdx.y * 32;
    int tx = threadIdx.x, ty = threadIdx.y;           // 32 x 8
#pragma unroll
    for (int j = 0; j < 32; j += 8) {
        int k = k0 + ty + j, n = n0 + tx;
        t[ty + j][tx] = (k < K) ? W[(size_t)k * HDIM + n] : 0.0f;
    }
    __syncthreads();
#pragma unroll
    for (int j = 0; j < 32; j += 8) {
        int n = n0 + ty + j, k = k0 + tx;
        if (k < K) g_WT[(size_t)n * K + k] = t[tx][ty + j];
    }
}

// ---------------------------------------------------------------------------
// TF32 mma.sync GEMM:  g_H[M,256] = op(A)[M,K] @ W[K,256]  (B from g_WT)
// CTA = 128x128, BK=16, 256 threads (8 warps as 2x4, 64x32/warp).
// ---------------------------------------------------------------------------
template <int K, bool RELU, int SEL>
__global__ void __launch_bounds__(256)
gemm_mma(const float* __restrict__ Ain, int M) {
    const float* A = (SEL == 0) ? Ain : g_A;
    float* Cout = g_H;

    __shared__ float As[2][128 * 16];
    __shared__ float Bs[2][128 * 16];

    const int tid = threadIdx.x;
    const int wid = tid >> 5, lane = tid & 31;
    const int warp_m = wid >> 2, warp_n = wid & 3;
    const int row0 = blockIdx.x * 128;
    const int col0 = blockIdx.y * 128;

    const uint32_t baseA = smem_u32(As);
    const uint32_t baseB = smem_u32(Bs);

    uint4 ra[2], rb[2];
    auto ld_g = [&](int t) {
#pragma unroll
        for (int j = 0; j < 2; j++) {
            int idx = j * 256 + tid;
            int r = idx >> 2, c = idx & 3;
            int gr = row0 + r;
            float4 v = make_float4(0.f, 0.f, 0.f, 0.f);
            if (gr < M) v = *(const float4*)&A[(size_t)gr * K + t * 16 + c * 4];
            if (RELU) {
                v.x = fmaxf(v.x, 0.f); v.y = fmaxf(v.y, 0.f);
                v.z = fmaxf(v.z, 0.f); v.w = fmaxf(v.w, 0.f);
            }
            ra[j].x = to_tf32(v.x); ra[j].y = to_tf32(v.y);
            ra[j].z = to_tf32(v.z); ra[j].w = to_tf32(v.w);
            float4 w = *(const float4*)&g_WT[(size_t)(col0 + r) * K + t * 16 + c * 4];
            rb[j].x = to_tf32(w.x); rb[j].y = to_tf32(w.y);
            rb[j].z = to_tf32(w.z); rb[j].w = to_tf32(w.w);
        }
    };
    auto st_s = [&](int b) {
#pragma unroll
        for (int j = 0; j < 2; j++) {
            int idx = j * 256 + tid;
            int r = idx >> 2, c = idx & 3;
            uint32_t off = (uint32_t)(r * 64 + ((c ^ ((r >> 1) & 3)) << 4));
            *(uint4*)((char*)As[b] + off) = ra[j];
            *(uint4*)((char*)Bs[b] + off) = rb[j];
        }
    };

    uint32_t a_row[4], a_sw[4];
#pragma unroll
    for (int mi = 0; mi < 4; mi++) {
        int row = warp_m * 64 + mi * 16 + ((lane >> 3) & 1) * 8 + (lane & 7);
        a_row[mi] = (uint32_t)(row * 64);
        a_sw[mi] = (uint32_t)((row >> 1) & 3);
    }
    const uint32_t a_chi = (uint32_t)((lane >> 4) & 1);
    uint32_t b_row[2], b_sw[2];
#pragma unroll
    for (int njp = 0; njp < 2; njp++) {
        int n = warp_n * 32 + njp * 16 + ((lane >> 4) & 1) * 8 + (lane & 7);
        b_row[njp] = (uint32_t)(n * 64);
        b_sw[njp] = (uint32_t)((n >> 1) & 3);
    }
    const uint32_t b_chi = (uint32_t)((lane >> 3) & 1);

    float acc[4][4][4];
#pragma unroll
    for (int mi = 0; mi < 4; mi++)
#pragma unroll
        for (int nj = 0; nj < 4; nj++)
#pragma unroll
            for (int i = 0; i < 4; i++) acc[mi][nj][i] = 0.0f;

    constexpr int NT = K / 16;

    ld_g(0);
    st_s(0);
    __syncthreads();

    for (int t = 0; t < NT; t++) {
        int cur = t & 1;
        bool more = (t + 1) < NT;
        if (more) ld_g(t + 1);

        uint32_t bA = baseA + (uint32_t)cur * 8192;
        uint32_t bB = baseB + (uint32_t)cur * 8192;
#pragma unroll
        for (int s = 0; s < 2; s++) {
            uint32_t af[4][4];
#pragma unroll
            for (int mi = 0; mi < 4; mi++) {
                uint32_t ch = 2 * s + a_chi;
                uint32_t addr = bA + a_row[mi] + ((ch ^ a_sw[mi]) << 4);
                ldsm_x4(af[mi][0], af[mi][1], af[mi][2], af[mi][3], addr);
            }
            uint32_t bf[4][2];
#pragma unroll
            for (int njp = 0; njp < 2; njp++) {
                uint32_t ch = 2 * s + b_chi;
                uint32_t addr = bB + b_row[njp] + ((ch ^ b_sw[njp]) << 4);
                uint32_t r0, r1, r2, r3;
                ldsm_x4(r0, r1, r2, r3, addr);
                bf[2 * njp][0] = r0;     bf[2 * njp][1] = r1;
                bf[2 * njp + 1][0] = r2; bf[2 * njp + 1][1] = r3;
            }
#pragma unroll
            for (int mi = 0; mi < 4; mi++)
#pragma unroll
                for (int nj = 0; nj < 4; nj++)
                    mma_tf32(acc[mi][nj], af[mi], bf[nj]);
        }

        if (more) st_s(cur ^ 1);
        __syncthreads();
    }

    const int g = lane >> 2, tg = lane & 3;
#pragma unroll
    for (int mi = 0; mi < 4; mi++) {
        int R0 = row0 + warp_m * 64 + mi * 16 + g;
        int R1 = R0 + 8;
#pragma unroll
        for (int nj = 0; nj < 4; nj++) {
            int cc = col0 + warp_n * 32 + nj * 8 + tg * 2;
            if (R0 < M)
                *(float2*)&Cout[(size_t)R0 * HDIM + cc] =
                    make_float2(acc[mi][nj][0], acc[mi][nj][1]);
            if (R1 < M)
                *(float2*)&Cout[(size_t)R1 * HDIM + cc] =
                    make_float2(acc[mi][nj][2], acc[mi][nj][3]);
        }
    }
}

// ---------------------------------------------------------------------------
// Gather aggregation: out[i,:] = bias + dinv_i^2*H[i,:] + sum_j norm*H[src_j,:]
// Warp per node, 32 lanes x 8 floats.
// ---------------------------------------------------------------------------
__global__ void __launch_bounds__(256)
gather_kernel(const float* __restrict__ bias, int n, int which) {
    int node = blockIdx.x * 8 + (threadIdx.x >> 5);
    if (node >= n) return;
    int lane = threadIdx.x & 31;
    int c0 = lane * 8;

    float* out = which ? g_A2 : g_A;
    float di = g_dinv[node];
    float s2 = di * di;

    float4 b0 = *(const float4*)&bias[c0];
    float4 b1 = *(const float4*)&bias[c0 + 4];
    float4 h0 = *(const float4*)&g_H[(size_t)node * HDIM + c0];
    float4 h1 = *(const float4*)&g_H[(size_t)node * HDIM + c0 + 4];
    float4 a0 = make_float4(b0.x + s2 * h0.x, b0.y + s2 * h0.y,
                            b0.z + s2 * h0.z, b0.w + s2 * h0.w);
    float4 a1 = make_float4(b1.x + s2 * h1.x, b1.y + s2 * h1.y,
                            b1.z + s2 * h1.z, b1.w + s2 * h1.w);

    int beg = g_rowptr[node], end = g_rowptr[node + 1];
    for (int j = beg; j < end; j++) {
        int s = g_srcs[j];
        float norm = di * g_dinv[s];
        float4 v0 = *(const float4*)&g_H[(size_t)s * HDIM + c0];
        float4 v1 = *(const float4*)&g_H[(size_t)s * HDIM + c0 + 4];
        a0.x += norm * v0.x; a0.y += norm * v0.y;
        a0.z += norm * v0.z; a0.w += norm * v0.w;
        a1.x += norm * v1.x; a1.y += norm * v1.y;
        a1.z += norm * v1.z; a1.w += norm * v1.w;
    }
    *(float4*)&out[(size_t)node * HDIM + c0]     = a0;
    *(float4*)&out[(size_t)node * HDIM + c0 + 4] = a1;
}

// ---------------------------------------------------------------------------
// Classifier GEMM: out[M,32] = relu(g_A2)[M,256] @ Wc + bc  (exact fp32)
// ---------------------------------------------------------------------------
template <int BM, int BN, int BK, int TM, int TN>
__global__ void gemm_small(const float* __restrict__ B,
                           const float* __restrict__ bias,
                           float* __restrict__ C_, int M, int K, int N) {
    constexpr int THREADS = (BM / TM) * (BN / TN);
    __shared__ float As[BK][BM + 4];
    __shared__ float Bs[BK][BN + 4];

    const int tid = threadIdx.x;
    const int tx = tid % (BN / TN);
    const int ty = tid / (BN / TN);
    const int row0 = blockIdx.x * BM;
    const int col0 = blockIdx.y * BN;

    float acc[TM][TN];
#pragma unroll
    for (int m = 0; m < TM; m++)
#pragma unroll
        for (int n = 0; n < TN; n++) acc[m][n] = 0.0f;

    for (int k0 = 0; k0 < K; k0 += BK) {
#pragma unroll
        for (int i = tid; i < BM * BK; i += THREADS) {
            int r = i / BK, c = i % BK;
            int gr = row0 + r;
            float v = (gr < M) ? g_A2[(size_t)gr * K + (k0 + c)] : 0.0f;
            As[c][r] = fmaxf(v, 0.0f);
        }
#pragma unroll
        for (int i = tid; i < BK * BN; i += THREADS) {
            int r = i / BN, c = i % BN;
            int gc = col0 + c;
            Bs[r][c] = (gc < N) ? B[(size_t)(k0 + r) * N + gc] : 0.0f;
        }
        __syncthreads();
#pragma unroll
        for (int kk = 0; kk < BK; kk++) {
            float ra[TM], rb[TN];
#pragma unroll
            for (int m = 0; m < TM; m++) ra[m] = As[kk][ty * TM + m];
#pragma unroll
            for (int n = 0; n < TN; n++) rb[n] = Bs[kk][tx * TN + n];
#pragma unroll
            for (int m = 0; m < TM; m++)
#pragma unroll
                for (int n = 0; n < TN; n++) acc[m][n] = fmaf(ra[m], rb[n], acc[m][n]);
        }
        __syncthreads();
    }
#pragma unroll
    for (int m = 0; m < TM; m++) {
        int gr = row0 + ty * TM + m;
        if (gr >= M) continue;
#pragma unroll
        for (int n = 0; n < TN; n++) {
            int gc = col0 + tx * TN + n;
            if (gc < N) C_[(size_t)gr * N + gc] = acc[m][n] + bias[gc];
        }
    }
}

// ---------------------------------------------------------------------------
// Launch
// ---------------------------------------------------------------------------
extern "C" void kernel_launch(void* const* d_in, const int* in_sizes, int n_in,
                              void* d_out, int out_size) {
    const float* x  = (const float*)d_in[0];
    const int* eidx = (const int*)d_in[1];
    const float* W1 = (const float*)d_in[2];
    const float* b1 = (const float*)d_in[3];
    const float* W2 = (const float*)d_in[4];
    const float* b2 = (const float*)d_in[5];
    const float* Wc = (const float*)d_in[6];
    const float* bc = (const float*)d_in[7];
    float* out = (float*)d_out;

    const int F_IN = 128;
    const int N = in_sizes[0] / F_IN;   // 50000
    const int E = in_sizes[1] / 2;      // 300000
    const int C = in_sizes[7];          // 32
    const int* src = eidx;
    const int* dst = eidx + E;

    // ---- CSR build (dst-major) + dinv ----
    zero_cnt_kernel<<<(N + 255) / 256, 256>>>(N);
    count_kernel<<<(E + 255) / 256, 256>>>(dst, E);
    scan_kernel<<<1, 1024>>>(N, E);
    fill_kernel<<<(E + 255) / 256, 256>>>(src, dst, E);

    const int RB = (N + 127) / 128;     // 391 row blocks
    dim3 ggrid(RB, HDIM / 128);         // 391 x 2
    const int GB = (N + 7) / 8;         // gather blocks

    // layer 1: g_H = X @ W1 ; g_A = gather(b1)
    wtrans_kernel<<<dim3(F_IN / 32, HDIM / 32), dim3(32, 8)>>>(W1, F_IN);
    gemm_mma<128, false, 0><<<ggrid, 256>>>(x, N);
    gather_kernel<<<GB, 256>>>(b1, N, 0);

    // layer 2: g_H = relu(g_A) @ W2 ; g_A2 = gather(b2)
    wtrans_kernel<<<dim3(HDIM / 32, HDIM / 32), dim3(32, 8)>>>(W2, HDIM);
    gemm_mma<256, true, 1><<<ggrid, 256>>>(nullptr, N);
    gather_kernel<<<GB, 256>>>(b2, N, 1);

    // classifier: out = relu(g_A2) @ Wc + bc (exact fp32)
    {
        dim3 grid((N + 63) / 64, (C + 31) / 32);
        gemm_small<64, 32, 16, 4, 2><<<grid, 256>>>(Wc, bc, out, N, HDIM, C);
    }
    (void)n_in; (void)out_size;
}

// round 13
// speedup vs baseline: 3.6603x; 1.1913x over previous
#include <cuda_runtime.h>
#include <cuda_bf16.h>
#include <math.h>
#include <stdint.h>

// Problem constants: N=50000 nodes, E=300000 edges, F_IN=128, H=256, C=32.
#define MAXN 50000
#define MAXE 300000
#define HDIM 256

// Scratch (no allocations allowed). Referenced ONLY from device code.
__device__ float g_dinv[MAXN];
__device__ int   g_cnt[MAXN];
__device__ int   g_pos[MAXN];
__device__ int   g_rowptr[MAXN + 1];
__device__ int   g_srcs[MAXE];
__device__ float g_H[MAXN * HDIM];    // GEMM output (messages source)
__device__ float g_A[MAXN * HDIM];    // layer-1 aggregate
__device__ float g_A2[MAXN * HDIM];   // layer-2 aggregate
__device__ float g_WT[HDIM * HDIM];   // transposed weights [n][k]

// ---------------------------------------------------------------------------
// Helpers
// ---------------------------------------------------------------------------
__device__ __forceinline__ uint32_t smem_u32(const void* p) {
    uint32_t a;
    asm("{ .reg .u64 t; cvta.to.shared.u64 t, %1; cvt.u32.u64 %0, t; }"
        : "=r"(a) : "l"(p));
    return a;
}
__device__ __forceinline__ uint32_t to_tf32(float x) {
    float r;
    asm("cvt.rna.tf32.f32 %0, %1;" : "=f"(r) : "f"(x));
    return __float_as_uint(r);
}
__device__ __forceinline__ void ldsm_x4(uint32_t& r0, uint32_t& r1,
                                        uint32_t& r2, uint32_t& r3,
                                        uint32_t addr) {
    asm volatile("ldmatrix.sync.aligned.m8n8.x4.shared.b16 {%0,%1,%2,%3}, [%4];"
                 : "=r"(r0), "=r"(r1), "=r"(r2), "=r"(r3) : "r"(addr));
}
__device__ __forceinline__ void mma_tf32(float* d, const uint32_t* a,
                                         const uint32_t* b) {
    asm volatile(
        "mma.sync.aligned.m16n8k8.row.col.f32.tf32.tf32.f32 "
        "{%0,%1,%2,%3}, {%4,%5,%6,%7}, {%8,%9}, {%0,%1,%2,%3};"
        : "+f"(d[0]), "+f"(d[1]), "+f"(d[2]), "+f"(d[3])
        : "r"(a[0]), "r"(a[1]), "r"(a[2]), "r"(a[3]), "r"(b[0]), "r"(b[1]));
}

// ---------------------------------------------------------------------------
// CSR build (dst-major) + dinv
// ---------------------------------------------------------------------------
__global__ void zero_cnt_kernel(int n) {
    int i = blockIdx.x * blockDim.x + threadIdx.x;
    if (i < n) { g_cnt[i] = 0; g_pos[i] = 0; }
}
__global__ void count_kernel(const int* __restrict__ dst, int e) {
    int i = blockIdx.x * blockDim.x + threadIdx.x;
    if (i < e) atomicAdd(&g_cnt[dst[i]], 1);
}
__global__ void scan_kernel(int n, int e) {
    __shared__ int part[1024];
    const int t = threadIdx.x;
    const int per = (n + 1023) / 1024;
    const int start = t * per;
    int sum = 0;
    for (int i = 0; i < per; i++) {
        int idx = start + i;
        if (idx < n) { g_rowptr[idx] = sum; sum += g_cnt[idx]; }
    }
    part[t] = sum;
    __syncthreads();
    for (int off = 1; off < 1024; off <<= 1) {
        int v = (t >= off) ? part[t - off] : 0;
        __syncthreads();
        part[t] += v;
        __syncthreads();
    }
    int offset = (t > 0) ? part[t - 1] : 0;
    for (int i = 0; i < per; i++) {
        int idx = start + i;
        if (idx < n) g_rowptr[idx] += offset;
    }
    if (t == 0) g_rowptr[n] = e;
    for (int i = t; i < n; i += 1024)
        g_dinv[i] = rsqrtf((float)g_cnt[i] + 1.0f);   // +1 self-loop
}
__global__ void fill_kernel(const int* __restrict__ src,
                            const int* __restrict__ dst, int e) {
    int i = blockIdx.x * blockDim.x + threadIdx.x;
    if (i < e) {
        int d = dst[i];
        int p = atomicAdd(&g_pos[d], 1);
        g_srcs[g_rowptr[d] + p] = src[i];
    }
}

// ---------------------------------------------------------------------------
// Weight transpose: g_WT[n][k] = W[k][n].  W is [K][NC].
// ---------------------------------------------------------------------------
__global__ void wtrans_kernel(const float* __restrict__ W, int K, int NC) {
    __shared__ float t[32][33];
    int k0 = blockIdx.x * 32, n0 = blockIdx.y * 32;
    int tx = threadIdx.x, ty = threadIdx.y;           // 32 x 8
#pragma unroll
    for (int j = 0; j < 32; j += 8) {
        int k = k0 + ty + j, n = n0 + tx;
        t[ty + j][tx] = (k < K && n < NC) ? W[(size_t)k * NC + n] : 0.0f;
    }
    __syncthreads();
#pragma unroll
    for (int j = 0; j < 32; j += 8) {
        int n = n0 + ty + j, k = k0 + tx;
        if (k < K && n < NC) g_WT[(size_t)n * K + k] = t[tx][ty + j];
    }
}

// ---------------------------------------------------------------------------
// TF32 mma.sync GEMM:  g_H[M,256] = op(A)[M,K] @ W[K,256]  (B from g_WT)
// CTA = 128x128, BK=16, 256 threads (8 warps as 2x4, 64x32/warp).
// ---------------------------------------------------------------------------
template <int K, bool RELU, int SEL>
__global__ void __launch_bounds__(256)
gemm_mma(const float* __restrict__ Ain, int M) {
    const float* A = (SEL == 0) ? Ain : g_A;
    float* Cout = g_H;

    __shared__ float As[2][128 * 16];
    __shared__ float Bs[2][128 * 16];

    const int tid = threadIdx.x;
    const int wid = tid >> 5, lane = tid & 31;
    const int warp_m = wid >> 2, warp_n = wid & 3;
    const int row0 = blockIdx.x * 128;
    const int col0 = blockIdx.y * 128;

    const uint32_t baseA = smem_u32(As);
    const uint32_t baseB = smem_u32(Bs);

    uint4 ra[2], rb[2];
    auto ld_g = [&](int t) {
#pragma unroll
        for (int j = 0; j < 2; j++) {
            int idx = j * 256 + tid;
            int r = idx >> 2, c = idx & 3;
            int gr = row0 + r;
            float4 v = make_float4(0.f, 0.f, 0.f, 0.f);
            if (gr < M) v = *(const float4*)&A[(size_t)gr * K + t * 16 + c * 4];
            if (RELU) {
                v.x = fmaxf(v.x, 0.f); v.y = fmaxf(v.y, 0.f);
                v.z = fmaxf(v.z, 0.f); v.w = fmaxf(v.w, 0.f);
            }
            ra[j].x = to_tf32(v.x); ra[j].y = to_tf32(v.y);
            ra[j].z = to_tf32(v.z); ra[j].w = to_tf32(v.w);
            float4 w = *(const float4*)&g_WT[(size_t)(col0 + r) * K + t * 16 + c * 4];
            rb[j].x = to_tf32(w.x); rb[j].y = to_tf32(w.y);
            rb[j].z = to_tf32(w.z); rb[j].w = to_tf32(w.w);
        }
    };
    auto st_s = [&](int b) {
#pragma unroll
        for (int j = 0; j < 2; j++) {
            int idx = j * 256 + tid;
            int r = idx >> 2, c = idx & 3;
            uint32_t off = (uint32_t)(r * 64 + ((c ^ ((r >> 1) & 3)) << 4));
            *(uint4*)((char*)As[b] + off) = ra[j];
            *(uint4*)((char*)Bs[b] + off) = rb[j];
        }
    };

    uint32_t a_row[4], a_sw[4];
#pragma unroll
    for (int mi = 0; mi < 4; mi++) {
        int row = warp_m * 64 + mi * 16 + ((lane >> 3) & 1) * 8 + (lane & 7);
        a_row[mi] = (uint32_t)(row * 64);
        a_sw[mi] = (uint32_t)((row >> 1) & 3);
    }
    const uint32_t a_chi = (uint32_t)((lane >> 4) & 1);
    uint32_t b_row[2], b_sw[2];
#pragma unroll
    for (int njp = 0; njp < 2; njp++) {
        int n = warp_n * 32 + njp * 16 + ((lane >> 4) & 1) * 8 + (lane & 7);
        b_row[njp] = (uint32_t)(n * 64);
        b_sw[njp] = (uint32_t)((n >> 1) & 3);
    }
    const uint32_t b_chi = (uint32_t)((lane >> 3) & 1);

    float acc[4][4][4];
#pragma unroll
    for (int mi = 0; mi < 4; mi++)
#pragma unroll
        for (int nj = 0; nj < 4; nj++)
#pragma unroll
            for (int i = 0; i < 4; i++) acc[mi][nj][i] = 0.0f;

    constexpr int NT = K / 16;

    ld_g(0);
    st_s(0);
    __syncthreads();

    for (int t = 0; t < NT; t++) {
        int cur = t & 1;
        bool more = (t + 1) < NT;
        if (more) ld_g(t + 1);

        uint32_t bA = baseA + (uint32_t)cur * 8192;
        uint32_t bB = baseB + (uint32_t)cur * 8192;
#pragma unroll
        for (int s = 0; s < 2; s++) {
            uint32_t af[4][4];
#pragma unroll
            for (int mi = 0; mi < 4; mi++) {
                uint32_t ch = 2 * s + a_chi;
                uint32_t addr = bA + a_row[mi] + ((ch ^ a_sw[mi]) << 4);
                ldsm_x4(af[mi][0], af[mi][1], af[mi][2], af[mi][3], addr);
            }
            uint32_t bf[4][2];
#pragma unroll
            for (int njp = 0; njp < 2; njp++) {
                uint32_t ch = 2 * s + b_chi;
                uint32_t addr = bB + b_row[njp] + ((ch ^ b_sw[njp]) << 4);
                uint32_t r0, r1, r2, r3;
                ldsm_x4(r0, r1, r2, r3, addr);
                bf[2 * njp][0] = r0;     bf[2 * njp][1] = r1;
                bf[2 * njp + 1][0] = r2; bf[2 * njp + 1][1] = r3;
            }
#pragma unroll
            for (int mi = 0; mi < 4; mi++)
#pragma unroll
                for (int nj = 0; nj < 4; nj++)
                    mma_tf32(acc[mi][nj], af[mi], bf[nj]);
        }

        if (more) st_s(cur ^ 1);
        __syncthreads();
    }

    const int g = lane >> 2, tg = lane & 3;
#pragma unroll
    for (int mi = 0; mi < 4; mi++) {
        int R0 = row0 + warp_m * 64 + mi * 16 + g;
        int R1 = R0 + 8;
#pragma unroll
        for (int nj = 0; nj < 4; nj++) {
            int cc = col0 + warp_n * 32 + nj * 8 + tg * 2;
            if (R0 < M)
                *(float2*)&Cout[(size_t)R0 * HDIM + cc] =
                    make_float2(acc[mi][nj][0], acc[mi][nj][1]);
            if (R1 < M)
                *(float2*)&Cout[(size_t)R1 * HDIM + cc] =
                    make_float2(acc[mi][nj][2], acc[mi][nj][3]);
        }
    }
}

// ---------------------------------------------------------------------------
// Classifier TF32 mma GEMM: out[M,32] = relu(g_A2)[M,256] @ Wc + bc.
// CTA = 128 rows x 32 cols, 256 threads (8 warps, 16 rows each). B from g_WT
// (WcT, [32][256]). Same ldmatrix/swizzle scheme as gemm_mma.
// ---------------------------------------------------------------------------
__global__ void __launch_bounds__(256)
gemm_cls(const float* __restrict__ bias, float* __restrict__ out, int M) {
    constexpr int K = 256;
    __shared__ float As[2][128 * 16];
    __shared__ float Bs[2][32 * 16];

    const int tid = threadIdx.x;
    const int wid = tid >> 5, lane = tid & 31;
    const int row0 = blockIdx.x * 128;

    const uint32_t baseA = smem_u32(As);
    const uint32_t baseB = smem_u32(Bs);

    uint4 ra[2], rb;
    auto ld_g = [&](int t) {
#pragma unroll
        for (int j = 0; j < 2; j++) {
            int idx = j * 256 + tid;
            int r = idx >> 2, c = idx & 3;
            int gr = row0 + r;
            float4 v = make_float4(0.f, 0.f, 0.f, 0.f);
            if (gr < M) v = *(const float4*)&g_A2[(size_t)gr * K + t * 16 + c * 4];
            v.x = fmaxf(v.x, 0.f); v.y = fmaxf(v.y, 0.f);
            v.z = fmaxf(v.z, 0.f); v.w = fmaxf(v.w, 0.f);
            ra[j].x = to_tf32(v.x); ra[j].y = to_tf32(v.y);
            ra[j].z = to_tf32(v.z); ra[j].w = to_tf32(v.w);
        }
        if (tid < 128) {
            int r = tid >> 2, c = tid & 3;
            float4 w = *(const float4*)&g_WT[(size_t)r * K + t * 16 + c * 4];
            rb.x = to_tf32(w.x); rb.y = to_tf32(w.y);
            rb.z = to_tf32(w.z); rb.w = to_tf32(w.w);
        }
    };
    auto st_s = [&](int b) {
#pragma unroll
        for (int j = 0; j < 2; j++) {
            int idx = j * 256 + tid;
            int r = idx >> 2, c = idx & 3;
            uint32_t off = (uint32_t)(r * 64 + ((c ^ ((r >> 1) & 3)) << 4));
            *(uint4*)((char*)As[b] + off) = ra[j];
        }
        if (tid < 128) {
            int r = tid >> 2, c = tid & 3;
            uint32_t off = (uint32_t)(r * 64 + ((c ^ ((r >> 1) & 3)) << 4));
            *(uint4*)((char*)Bs[b] + off) = rb;
        }
    };

    // A frag addressing: warp owns rows wid*16 .. wid*16+15.
    int a_r = wid * 16 + ((lane >> 3) & 1) * 8 + (lane & 7);
    const uint32_t a_row = (uint32_t)(a_r * 64);
    const uint32_t a_sw = (uint32_t)((a_r >> 1) & 3);
    const uint32_t a_chi = (uint32_t)((lane >> 4) & 1);
    // B frags: njp 0..1 cover n 0..31.
    uint32_t b_row[2], b_sw[2];
#pragma unroll
    for (int njp = 0; njp < 2; njp++) {
        int n = njp * 16 + ((lane >> 4) & 1) * 8 + (lane & 7);
        b_row[njp] = (uint32_t)(n * 64);
        b_sw[njp] = (uint32_t)((n >> 1) & 3);
    }
    const uint32_t b_chi = (uint32_t)((lane >> 3) & 1);

    float acc[4][4];
#pragma unroll
    for (int nj = 0; nj < 4; nj++)
#pragma unroll
        for (int i = 0; i < 4; i++) acc[nj][i] = 0.0f;

    constexpr int NT = K / 16;

    ld_g(0);
    st_s(0);
    __syncthreads();

    for (int t = 0; t < NT; t++) {
        int cur = t & 1;
        bool more = (t + 1) < NT;
        if (more) ld_g(t + 1);

        uint32_t bA = baseA + (uint32_t)cur * 8192;
        uint32_t bB = baseB + (uint32_t)cur * 2048;
#pragma unroll
        for (int s = 0; s < 2; s++) {
            uint32_t af[4];
            {
                uint32_t ch = 2 * s + a_chi;
                uint32_t addr = bA + a_row + ((ch ^ a_sw) << 4);
                ldsm_x4(af[0], af[1], af[2], af[3], addr);
            }
            uint32_t bf[4][2];
#pragma unroll
            for (int njp = 0; njp < 2; njp++) {
                uint32_t ch = 2 * s + b_chi;
                uint32_t addr = bB + b_row[njp] + ((ch ^ b_sw[njp]) << 4);
                uint32_t r0, r1, r2, r3;
                ldsm_x4(r0, r1, r2, r3, addr);
                bf[2 * njp][0] = r0;     bf[2 * njp][1] = r1;
                bf[2 * njp + 1][0] = r2; bf[2 * njp + 1][1] = r3;
            }
#pragma unroll
            for (int nj = 0; nj < 4; nj++)
                mma_tf32(acc[nj], af, bf[nj]);
        }

        if (more) st_s(cur ^ 1);
        __syncthreads();
    }

    const int g = lane >> 2, tg = lane & 3;
    int R0 = row0 + wid * 16 + g;
    int R1 = R0 + 8;
#pragma unroll
    for (int nj = 0; nj < 4; nj++) {
        int cc = nj * 8 + tg * 2;
        float2 bb = *(const float2*)&bias[cc];
        if (R0 < M)
            *(float2*)&out[(size_t)R0 * 32 + cc] =
                make_float2(acc[nj][0] + bb.x, acc[nj][1] + bb.y);
        if (R1 < M)
            *(float2*)&out[(size_t)R1 * 32 + cc] =
                make_float2(acc[nj][2] + bb.x, acc[nj][3] + bb.y);
    }
}

// ---------------------------------------------------------------------------
// Gather aggregation: out[i,:] = bias + dinv_i^2*H[i,:] + sum_j norm*H[src_j,:]
// Warp per node, 32 lanes x 8 floats.
// ---------------------------------------------------------------------------
__global__ void __launch_bounds__(256)
gather_kernel(const float* __restrict__ bias, int n, int which) {
    int node = blockIdx.x * 8 + (threadIdx.x >> 5);
    if (node >= n) return;
    int lane = threadIdx.x & 31;
    int c0 = lane * 8;

    float* out = which ? g_A2 : g_A;
    float di = g_dinv[node];
    float s2 = di * di;

    float4 b0 = *(const float4*)&bias[c0];
    float4 b1 = *(const float4*)&bias[c0 + 4];
    float4 h0 = *(const float4*)&g_H[(size_t)node * HDIM + c0];
    float4 h1 = *(const float4*)&g_H[(size_t)node * HDIM + c0 + 4];
    float4 a0 = make_float4(b0.x + s2 * h0.x, b0.y + s2 * h0.y,
                            b0.z + s2 * h0.z, b0.w + s2 * h0.w);
    float4 a1 = make_float4(b1.x + s2 * h1.x, b1.y + s2 * h1.y,
                            b1.z + s2 * h1.z, b1.w + s2 * h1.w);

    int beg = g_rowptr[node], end = g_rowptr[node + 1];
    for (int j = beg; j < end; j++) {
        int s = g_srcs[j];
        float norm = di * g_dinv[s];
        float4 v0 = *(const float4*)&g_H[(size_t)s * HDIM + c0];
        float4 v1 = *(const float4*)&g_H[(size_t)s * HDIM + c0 + 4];
        a0.x += norm * v0.x; a0.y += norm * v0.y;
        a0.z += norm * v0.z; a0.w += norm * v0.w;
        a1.x += norm * v1.x; a1.y += norm * v1.y;
        a1.z += norm * v1.z; a1.w += norm * v1.w;
    }
    *(float4*)&out[(size_t)node * HDIM + c0]     = a0;
    *(float4*)&out[(size_t)node * HDIM + c0 + 4] = a1;
}

// ---------------------------------------------------------------------------
// Launch
// ---------------------------------------------------------------------------
extern "C" void kernel_launch(void* const* d_in, const int* in_sizes, int n_in,
                              void* d_out, int out_size) {
    const float* x  = (const float*)d_in[0];
    const int* eidx = (const int*)d_in[1];
    const float* W1 = (const float*)d_in[2];
    const float* b1 = (const float*)d_in[3];
    const float* W2 = (const float*)d_in[4];
    const float* b2 = (const float*)d_in[5];
    const float* Wc = (const float*)d_in[6];
    const float* bc = (const float*)d_in[7];
    float* out = (float*)d_out;

    const int F_IN = 128;
    const int N = in_sizes[0] / F_IN;   // 50000
    const int E = in_sizes[1] / 2;      // 300000
    const int* src = eidx;
    const int* dst = eidx + E;

    // ---- CSR build (dst-major) + dinv ----
    zero_cnt_kernel<<<(N + 255) / 256, 256>>>(N);
    count_kernel<<<(E + 255) / 256, 256>>>(dst, E);
    scan_kernel<<<1, 1024>>>(N, E);
    fill_kernel<<<(E + 255) / 256, 256>>>(src, dst, E);

    const int RB = (N + 127) / 128;     // 391 row blocks
    dim3 ggrid(RB, HDIM / 128);         // 391 x 2
    const int GB = (N + 7) / 8;         // gather blocks

    // layer 1: g_H = X @ W1 ; g_A = gather(b1)
    wtrans_kernel<<<dim3(F_IN / 32, HDIM / 32), dim3(32, 8)>>>(W1, F_IN, HDIM);
    gemm_mma<128, false, 0><<<ggrid, 256>>>(x, N);
    gather_kernel<<<GB, 256>>>(b1, N, 0);

    // layer 2: g_H = relu(g_A) @ W2 ; g_A2 = gather(b2)
    wtrans_kernel<<<dim3(HDIM / 32, HDIM / 32), dim3(32, 8)>>>(W2, HDIM, HDIM);
    gemm_mma<256, true, 1><<<ggrid, 256>>>(nullptr, N);
    gather_kernel<<<GB, 256>>>(b2, N, 1);

    // classifier: out = relu(g_A2) @ Wc + bc (tf32 mma)
    wtrans_kernel<<<dim3(HDIM / 32, 1), dim3(32, 8)>>>(Wc, HDIM, 32);
    gemm_cls<<<RB, 256>>>(bc, out, N);

    (void)n_in; (void)out_size;
}